// round 2
// baseline (speedup 1.0000x reference)
#include <cuda_runtime.h>
#include <math.h>
#include <stdint.h>

// Problem constants (fixed by setup_inputs)
#define HEADS  24
#define HDIM   32
#define TT     16
#define S_SP   1560            // th*tw = 30*52
#define BATCH  2
#define CDIM   768
#define INMLP  792             // C + PAD_T*mouse_dim = 768 + 24
#define NROWS  (BATCH*S_SP*TT) // 49920
#define NF     61              // (tt-1)*R+1
#define PADT   12

// Scratch (static device globals; no runtime allocation)
__device__ float g_z   [(size_t)NROWS * INMLP];
__device__ float g_h   [(size_t)NROWS * INMLP];
__device__ float g_feat[(size_t)NROWS * CDIM];
__device__ float g_qkv [(size_t)NROWS * 3 * CDIM];
__device__ float g_attn[(size_t)NROWS * CDIM];

// ---------------------------------------------------------------------------
// Kernel 1: build z = concat(hs, gathered mouse)   (49920 x 792)
// row r = (b*S + s)*TT + t ;  hs part = x[b, t*S + s, :]
// ---------------------------------------------------------------------------
__global__ void build_z_kernel(const float* __restrict__ x,
                               const float* __restrict__ mouse)
{
    int r = blockIdx.x;
    int bs = r / TT, t = r % TT;
    int b_idx = bs / S_SP, s = bs % S_SP;

    const float4* xr = reinterpret_cast<const float4*>(
        x + ((size_t)b_idx * (TT * S_SP) + (size_t)t * S_SP + s) * CDIM);
    float* zr = g_z + (size_t)r * INMLP;
    float4* zr4 = reinterpret_cast<float4*>(zr);

    for (int c = threadIdx.x; c < CDIM / 4; c += blockDim.x)
        zr4[c] = xr[c];

    if (threadIdx.x < 24) {
        int j  = threadIdx.x >> 1;   // 0..11
        int ch = threadIdx.x & 1;    // 0..1
        int i  = 4 * t + j;          // padded index (R=4)
        float v = 0.0f;
        if (i >= PADT) v = mouse[((size_t)b_idx * NF + (i - PADT)) * 2 + ch];
        zr[CDIM + threadIdx.x] = v;
    }
}

// ---------------------------------------------------------------------------
// SGEMM: C = A(MxK) * B(KxN) + epilogue
// EPI: 0 none, 1 +bias, 2 +bias then gelu(tanh), 3 +residual(res)
// A is selected from device globals via a_sel; C via c_sel (4 = external ptr)
// BM=BN=128, BK=8, 256 threads, 8x8 per thread. M % 128 == 0, K % 8 == 0,
// K % 4 == 0, N % 4 == 0 guaranteed by problem shapes; N edge guarded.
// ---------------------------------------------------------------------------
template<int EPI>
__global__ __launch_bounds__(256)
void sgemm_kernel(int a_sel, const float* __restrict__ B,
                  const float* __restrict__ bias,
                  const float* __restrict__ res,
                  float* __restrict__ Cext, int c_sel,
                  int M, int N, int K)
{
    const float* A = (a_sel == 0) ? g_z :
                     (a_sel == 1) ? g_h :
                     (a_sel == 2) ? g_feat : g_attn;
    float* C = (c_sel == 0) ? g_h :
               (c_sel == 1) ? g_feat :
               (c_sel == 2) ? g_qkv :
               (c_sel == 3) ? g_attn : Cext;

    const int BM = 128, BN = 128, BK = 8, TM = 8, TN = 8;
    __shared__ float As[BK][BM];
    __shared__ float Bs[BK][BN];

    int tid  = threadIdx.x;
    int bcol = blockIdx.x * BN;
    int brow = blockIdx.y * BM;
    int trow = (tid / 16) * TM;
    int tcol = (tid % 16) * TN;

    int a_row = tid >> 1;
    int a_col = (tid & 1) * 4;
    int b_row = tid >> 5;
    int b_col = (tid & 31) * 4;

    float acc[TM][TN] = {};

    const float* Aptr = A + (size_t)(brow + a_row) * K + a_col;
    const float* Bptr = B + (size_t)b_row * N + bcol + b_col;
    bool bvalid = (bcol + b_col) < N;   // N % 4 == 0 -> all-or-nothing float4

    for (int k0 = 0; k0 < K; k0 += BK) {
        float4 av = *reinterpret_cast<const float4*>(Aptr + k0);
        As[a_col + 0][a_row] = av.x;
        As[a_col + 1][a_row] = av.y;
        As[a_col + 2][a_row] = av.z;
        As[a_col + 3][a_row] = av.w;

        float4 bv = make_float4(0.f, 0.f, 0.f, 0.f);
        if (bvalid) bv = *reinterpret_cast<const float4*>(Bptr + (size_t)k0 * N);
        *reinterpret_cast<float4*>(&Bs[b_row][b_col]) = bv;

        __syncthreads();

        #pragma unroll
        for (int kk = 0; kk < BK; kk++) {
            float4 a0 = *reinterpret_cast<const float4*>(&As[kk][trow]);
            float4 a1 = *reinterpret_cast<const float4*>(&As[kk][trow + 4]);
            float4 b0 = *reinterpret_cast<const float4*>(&Bs[kk][tcol]);
            float4 b1 = *reinterpret_cast<const float4*>(&Bs[kk][tcol + 4]);
            float af[TM] = {a0.x, a0.y, a0.z, a0.w, a1.x, a1.y, a1.z, a1.w};
            float bf[TN] = {b0.x, b0.y, b0.z, b0.w, b1.x, b1.y, b1.z, b1.w};
            #pragma unroll
            for (int i = 0; i < TM; i++)
                #pragma unroll
                for (int j = 0; j < TN; j++)
                    acc[i][j] = fmaf(af[i], bf[j], acc[i][j]);
        }
        __syncthreads();
    }

    #pragma unroll
    for (int i = 0; i < TM; i++) {
        int row = brow + trow + i;
        #pragma unroll
        for (int j = 0; j < TN; j++) {
            int col = bcol + tcol + j;
            if (col >= N) continue;
            float v = acc[i][j];
            if (EPI == 1) v += bias[col];
            if (EPI == 2) {
                v += bias[col];
                float u = 0.7978845608028654f * (v + 0.044715f * v * v * v);
                v = 0.5f * v * (1.0f + tanhf(u));
            }
            if (EPI == 3) v += res[(size_t)row * N + col];
            C[(size_t)row * N + col] = v;
        }
    }
}

// ---------------------------------------------------------------------------
// Attention: one warp per (bs, head). q,k,v are (TT=16, 32).
// RMSNorm(q,k) -> RoPE (first 24 dims temporal, last 8 identity) ->
// softmax(q k^T / sqrt(32)) v. Output written in (b, t*S+s) row order.
// ---------------------------------------------------------------------------
__global__ __launch_bounds__(128)
void attn_kernel(const float* __restrict__ q_gamma,
                 const float* __restrict__ k_gamma)
{
    __shared__ float qs[4][TT][33];
    __shared__ float ks[4][TT][33];
    __shared__ float vs[4][TT][32];
    __shared__ float ps[4][TT][17];

    int warp = threadIdx.x >> 5;
    int lane = threadIdx.x & 31;
    int gw = blockIdx.x * 4 + warp;           // 0 .. 74879
    int head = gw % HEADS;
    int bs   = gw / HEADS;
    int b_idx = bs / S_SP;
    int s     = bs % S_SP;

    float q[TT], k[TT], v[TT];
    #pragma unroll
    for (int t = 0; t < TT; t++) {
        size_t base = ((size_t)(bs * TT + t)) * (3 * CDIM) + head * HDIM + lane;
        q[t] = g_qkv[base];
        k[t] = g_qkv[base + CDIM];
        v[t] = g_qkv[base + 2 * CDIM];
    }

    float qg = q_gamma[lane], kg = k_gamma[lane];
    float freq = 0.0f;
    if (lane < 24) {
        int p = lane >> 1;                    // pair index 0..11
        freq = exp2f(-8.0f * (float)(2 * p) / 24.0f);  // 256^(-2p/24)
    }

    #pragma unroll
    for (int t = 0; t < TT; t++) {
        float sq = q[t] * q[t];
        float sk = k[t] * k[t];
        #pragma unroll
        for (int o = 16; o > 0; o >>= 1) {
            sq += __shfl_xor_sync(0xffffffffu, sq, o);
            sk += __shfl_xor_sync(0xffffffffu, sk, o);
        }
        float qn = q[t] * rsqrtf(sq * (1.0f / 32.0f) + 1e-6f) * qg;
        float kn = k[t] * rsqrtf(sk * (1.0f / 32.0f) + 1e-6f) * kg;

        float c = 1.0f, sn = 0.0f;
        if (lane < 24) {
            float ang = freq * (float)t;
            c = cosf(ang);
            sn = sinf(ang);
        }
        float qr = __shfl_xor_sync(0xffffffffu, qn, 1);
        float kr = __shfl_xor_sync(0xffffffffu, kn, 1);
        qr = (lane & 1) ? qr : -qr;           // rotate_half
        kr = (lane & 1) ? kr : -kr;

        qs[warp][t][lane] = qn * c + qr * sn;
        ks[warp][t][lane] = kn * c + kr * sn;
        vs[warp][t][lane] = v[t];
    }
    __syncwarp();

    const float scale = 0.17677669529663687f;  // 32^-0.5
    #pragma unroll
    for (int i = 0; i < 8; i++) {
        int idx = lane * 8 + i;
        int t = idx >> 4, m = idx & 15;
        float sum = 0.0f;
        #pragma unroll
        for (int d = 0; d < HDIM; d++)
            sum = fmaf(qs[warp][t][d], ks[warp][m][d], sum);
        ps[warp][t][m] = sum * scale;
    }
    __syncwarp();

    if (lane < 16) {
        float mx = -1e30f;
        #pragma unroll
        for (int m = 0; m < 16; m++) mx = fmaxf(mx, ps[warp][lane][m]);
        float sum = 0.0f;
        #pragma unroll
        for (int m = 0; m < 16; m++) {
            float e = expf(ps[warp][lane][m] - mx);
            ps[warp][lane][m] = e;
            sum += e;
        }
        float inv = 1.0f / sum;
        #pragma unroll
        for (int m = 0; m < 16; m++) ps[warp][lane][m] *= inv;
    }
    __syncwarp();

    #pragma unroll
    for (int t = 0; t < TT; t++) {
        float o = 0.0f;
        #pragma unroll
        for (int m = 0; m < 16; m++)
            o = fmaf(ps[warp][t][m], vs[warp][m][lane], o);
        size_t orow = (size_t)b_idx * (TT * S_SP) + (size_t)t * S_SP + s;
        g_attn[orow * CDIM + head * HDIM + lane] = o;
    }
}

// ---------------------------------------------------------------------------
extern "C" void kernel_launch(void* const* d_in, const int* in_sizes, int n_in,
                              void* d_out, int out_size)
{
    const float* mouse = (const float*)d_in[0];
    // d_in[1] = keyboard_condition (unused by reference)
    const float* x     = (const float*)d_in[2];
    const float* w1    = (const float*)d_in[3];
    const float* b1    = (const float*)d_in[4];
    const float* w2    = (const float*)d_in[5];
    const float* b2    = (const float*)d_in[6];
    const float* qkvw  = (const float*)d_in[7];
    const float* qg    = (const float*)d_in[8];
    const float* kg    = (const float*)d_in[9];
    const float* pw    = (const float*)d_in[10];
    float* out = (float*)d_out;

    // 1) gather z
    build_z_kernel<<<NROWS, 128>>>(x, mouse);

    // 2) h = gelu(z @ w1 + b1)              (49920 x 792) @ (792 x 792)
    {
        dim3 grid((INMLP + 127) / 128, NROWS / 128);
        sgemm_kernel<2><<<grid, 256>>>(0, w1, b1, nullptr, nullptr, 0,
                                       NROWS, INMLP, INMLP);
    }
    // 3) feat = h @ w2 + b2                 (49920 x 792) @ (792 x 768)
    {
        dim3 grid(CDIM / 128, NROWS / 128);
        sgemm_kernel<1><<<grid, 256>>>(1, w2, b2, nullptr, nullptr, 1,
                                       NROWS, CDIM, INMLP);
    }
    // 4) qkv = feat @ qkv_w                 (49920 x 768) @ (768 x 2304)
    {
        dim3 grid((3 * CDIM) / 128, NROWS / 128);
        sgemm_kernel<0><<<grid, 256>>>(2, qkvw, nullptr, nullptr, nullptr, 2,
                                       NROWS, 3 * CDIM, CDIM);
    }
    // 5) attention -> g_attn (already permuted back to x row order)
    attn_kernel<<<(BATCH * S_SP * HEADS) / 4, 128>>>(qg, kg);

    // 6) out = x + g_attn @ proj_w          (49920 x 768) @ (768 x 768)
    {
        dim3 grid(CDIM / 128, NROWS / 128);
        sgemm_kernel<3><<<grid, 256>>>(3, pw, nullptr, x, out, 4,
                                       NROWS, CDIM, CDIM);
    }
    (void)in_sizes; (void)n_in; (void)out_size;
}

// round 5
// speedup vs baseline: 2.3934x; 2.3934x over previous
#include <cuda_runtime.h>
#include <cuda_bf16.h>
#include <math.h>
#include <stdint.h>

// Problem constants (fixed by setup_inputs)
#define HEADS  24
#define HDIM   32
#define TT     16
#define S_SP   1560            // th*tw
#define BATCH  2
#define CDIM   768
#define INMLP  792
#define NROWS  (BATCH*S_SP*TT) // 49920
#define NF     61
#define PADT   12

// ---------------------------------------------------------------------------
// Scratch (static device globals; no runtime allocation)
// ---------------------------------------------------------------------------
__device__ float g_z   [(size_t)NROWS * INMLP];
__device__ float g_h   [(size_t)NROWS * INMLP];
__device__ float g_feat[(size_t)NROWS * CDIM];
__device__ float g_qkv [(size_t)NROWS * 3 * CDIM];
__device__ float g_attn[(size_t)NROWS * CDIM];

// Pre-transposed, hi/lo-split weights: [Npad][Kpad] bf16, K contiguous
__device__ __nv_bfloat16 g_w1h[(size_t)1024 * 832];
__device__ __nv_bfloat16 g_w1l[(size_t)1024 * 832];
__device__ __nv_bfloat16 g_w2h[(size_t)768  * 832];
__device__ __nv_bfloat16 g_w2l[(size_t)768  * 832];
__device__ __nv_bfloat16 g_w3h[(size_t)2304 * 768];
__device__ __nv_bfloat16 g_w3l[(size_t)2304 * 768];
__device__ __nv_bfloat16 g_w4h[(size_t)768  * 768];
__device__ __nv_bfloat16 g_w4l[(size_t)768  * 768];

// ---------------------------------------------------------------------------
// helpers
// ---------------------------------------------------------------------------
__device__ __forceinline__ uint32_t s2u(const void* p) {
    uint32_t a;
    asm("{ .reg .u64 t; cvta.to.shared.u64 t, %1; cvt.u32.u64 %0, t; }"
        : "=r"(a) : "l"(p));
    return a;
}

__device__ __forceinline__ void ldsm4(uint32_t* r, uint32_t a) {
    asm volatile("ldmatrix.sync.aligned.m8n8.x4.shared.b16 {%0,%1,%2,%3}, [%4];"
        : "=r"(r[0]), "=r"(r[1]), "=r"(r[2]), "=r"(r[3]) : "r"(a));
}

__device__ __forceinline__ void mma_bf16(float* d, const uint32_t* a,
                                         const uint32_t* b) {
    asm volatile(
        "mma.sync.aligned.m16n8k16.row.col.f32.bf16.bf16.f32 "
        "{%0,%1,%2,%3}, {%4,%5,%6,%7}, {%8,%9}, {%0,%1,%2,%3};"
        : "+f"(d[0]), "+f"(d[1]), "+f"(d[2]), "+f"(d[3])
        : "r"(a[0]), "r"(a[1]), "r"(a[2]), "r"(a[3]), "r"(b[0]), "r"(b[1]));
}

// pack two fp32 into bf16x2 (lo element -> low 16 bits)
__device__ __forceinline__ uint32_t pack_bf(float e0, float e1) {
    uint32_t r;
    asm("cvt.rn.bf16x2.f32 %0, %1, %2;" : "=r"(r) : "f"(e1), "f"(e0));
    return r;
}
__device__ __forceinline__ float bf_hi_val(float x) {
    return __bfloat162float(__float2bfloat16(x));
}

// ---------------------------------------------------------------------------
// Weight transpose + hi/lo split: W(K x N fp32) -> [Npad][Kpad] bf16
// ---------------------------------------------------------------------------
__global__ void conv_weight(const float* __restrict__ W,
                            __nv_bfloat16* __restrict__ hi,
                            __nv_bfloat16* __restrict__ lo,
                            int K, int N, int Kpad) {
    __shared__ float t[32][33];
    int n0 = blockIdx.x * 32, k0 = blockIdx.y * 32;
    int tx = threadIdx.x, ty = threadIdx.y;  // 32 x 8
    #pragma unroll
    for (int j = 0; j < 32; j += 8) {
        int k = k0 + ty + j, n = n0 + tx;
        t[ty + j][tx] = (k < K && n < N) ? W[(size_t)k * N + n] : 0.0f;
    }
    __syncthreads();
    #pragma unroll
    for (int j = 0; j < 32; j += 8) {
        int n = n0 + ty + j, k = k0 + tx;
        float v = t[tx][ty + j];
        __nv_bfloat16 h = __float2bfloat16(v);
        hi[(size_t)n * Kpad + k] = h;
        lo[(size_t)n * Kpad + k] = __float2bfloat16(v - __bfloat162float(h));
    }
}

// ---------------------------------------------------------------------------
// build z = concat(hs, gathered mouse)
// ---------------------------------------------------------------------------
__global__ void build_z_kernel(const float* __restrict__ x,
                               const float* __restrict__ mouse) {
    int r = blockIdx.x;
    int bs = r / TT, t = r % TT;
    int b_idx = bs / S_SP, s = bs % S_SP;

    const float4* xr = reinterpret_cast<const float4*>(
        x + ((size_t)b_idx * (TT * S_SP) + (size_t)t * S_SP + s) * CDIM);
    float* zr = g_z + (size_t)r * INMLP;
    float4* zr4 = reinterpret_cast<float4*>(zr);

    for (int c = threadIdx.x; c < CDIM / 4; c += blockDim.x)
        zr4[c] = xr[c];

    if (threadIdx.x < 24) {
        int j  = threadIdx.x >> 1;
        int ch = threadIdx.x & 1;
        int i  = 4 * t + j;
        float v = 0.0f;
        if (i >= PADT) v = mouse[((size_t)b_idx * NF + (i - PADT)) * 2 + ch];
        zr[CDIM + threadIdx.x] = v;
    }
}

// ---------------------------------------------------------------------------
// bf16 split GEMM on HMMA (mma.sync): C = A * W + epilogue
// CTA 128x128, BK=32, 8 warps (2x4), warp tile 64x32, double-buffered SMEM.
// 3 passes: Ahi*Bhi + Alo*Bhi + Ahi*Blo.
// EPI: 0 none, 1 +bias, 2 +bias+gelu, 3 +residual
// ---------------------------------------------------------------------------
#define OFF_AH 0
#define OFF_AL 8192
#define OFF_BH 16384
#define OFF_BL 24576
#define STAGE  32768
#define SMEM_SZ (2*STAGE)

template<int EPI>
__global__ void __launch_bounds__(256, 1)
mma_gemm(const float* __restrict__ A,
         const __nv_bfloat16* __restrict__ Bhg,
         const __nv_bfloat16* __restrict__ Blg,
         const float* __restrict__ bias,
         const float* __restrict__ res,
         float* __restrict__ C,
         int Nact, int Kact, int Kpad, int ldA, int ldC)
{
    extern __shared__ char smem[];
    const uint32_t sb = s2u(smem);
    const int tid = threadIdx.x, wid = tid >> 5, lane = tid & 31;
    const int m0 = blockIdx.y * 128, n0 = blockIdx.x * 128;
    const int wr = wid & 1, wc = wid >> 1;

    // prefetch index helpers
    const int ar = tid >> 1;             // A row 0..127
    const int ah = (tid & 1) << 4;       // k offset 0/16 within chunk
    float a_pf[16];
    uint4 bh_pf[2], bl_pf[2];

    const int NCH = Kpad >> 5;

    auto load_gmem = [&](int c) {
        const int k0 = c * 32;
        const float* Ap = A + (size_t)(m0 + ar) * ldA + k0 + ah;
        #pragma unroll
        for (int q = 0; q < 4; q++) {
            int k = k0 + ah + q * 4;
            float4 v = make_float4(0.f, 0.f, 0.f, 0.f);
            if (k < Kact) v = *reinterpret_cast<const float4*>(Ap + q * 4);
            a_pf[q*4+0] = v.x; a_pf[q*4+1] = v.y;
            a_pf[q*4+2] = v.z; a_pf[q*4+3] = v.w;
        }
        #pragma unroll
        for (int i = 0; i < 2; i++) {
            int idx = i * 256 + tid;
            int rn = idx >> 2, sg = idx & 3;
            size_t o = (size_t)(n0 + rn) * Kpad + k0 + sg * 8;
            bh_pf[i] = *reinterpret_cast<const uint4*>(Bhg + o);
            bl_pf[i] = *reinterpret_cast<const uint4*>(Blg + o);
        }
    };

    auto store_smem = [&](int stg) {
        char* st = smem + stg * STAGE;
        const int swa = (ar >> 1) & 3;
        #pragma unroll
        for (int j = 0; j < 2; j++) {
            // 8 floats -> 4 u32 hi, 4 u32 lo
            uint32_t h[4], l[4];
            #pragma unroll
            for (int q = 0; q < 4; q++) {
                float f0 = a_pf[j*8 + q*2], f1 = a_pf[j*8 + q*2 + 1];
                h[q] = pack_bf(f0, f1);
                l[q] = pack_bf(f0 - bf_hi_val(f0), f1 - bf_hi_val(f1));
            }
            int seg = (ah >> 3) + j;
            uint32_t off = (uint32_t)(ar * 64 + ((seg ^ swa) << 4));
            *reinterpret_cast<uint4*>(st + OFF_AH + off) =
                make_uint4(h[0], h[1], h[2], h[3]);
            *reinterpret_cast<uint4*>(st + OFF_AL + off) =
                make_uint4(l[0], l[1], l[2], l[3]);
        }
        #pragma unroll
        for (int i = 0; i < 2; i++) {
            int idx = i * 256 + tid;
            int rn = idx >> 2, sg = idx & 3;
            uint32_t off = (uint32_t)(rn * 64 + ((sg ^ ((rn >> 1) & 3)) << 4));
            *reinterpret_cast<uint4*>(st + OFF_BH + off) = bh_pf[i];
            *reinterpret_cast<uint4*>(st + OFF_BL + off) = bl_pf[i];
        }
    };

    float acc[4][4][4] = {};

    // ldmatrix per-thread constants
    const int a_r = lane & 15;           // row within m16
    const int a_s = lane >> 4;           // kseg half (0/1)
    const int b_n = (lane & 7) + ((lane >> 4) << 3);
    const int b_s = (lane >> 3) & 1;

    load_gmem(0);
    store_smem(0);
    __syncthreads();

    for (int c = 0; c < NCH; c++) {
        const int cur = c & 1;
        if (c + 1 < NCH) load_gmem(c + 1);

        const uint32_t st = sb + cur * STAGE;
        #pragma unroll
        for (int step = 0; step < 2; step++) {
            uint32_t Ah[4][4], Al[4][4], Bh2[2][4], Bl2[2][4];
            #pragma unroll
            for (int mi = 0; mi < 4; mi++) {
                int row = wr * 64 + mi * 16 + a_r;
                int ks = step * 2 + a_s;
                uint32_t off = (uint32_t)(row * 64 +
                               ((ks ^ ((row >> 1) & 3)) << 4));
                ldsm4(Ah[mi], st + OFF_AH + off);
                ldsm4(Al[mi], st + OFF_AL + off);
            }
            #pragma unroll
            for (int np = 0; np < 2; np++) {
                int row = wc * 32 + np * 16 + b_n;
                int ks = step * 2 + b_s;
                uint32_t off = (uint32_t)(row * 64 +
                               ((ks ^ ((row >> 1) & 3)) << 4));
                ldsm4(Bh2[np], st + OFF_BH + off);
                ldsm4(Bl2[np], st + OFF_BL + off);
            }
            // pass-major to avoid back-to-back dependent MMAs on same acc
            #pragma unroll
            for (int mi = 0; mi < 4; mi++)
                #pragma unroll
                for (int ni = 0; ni < 4; ni++)
                    mma_bf16(acc[mi][ni], Ah[mi], &Bh2[ni >> 1][(ni & 1) * 2]);
            #pragma unroll
            for (int mi = 0; mi < 4; mi++)
                #pragma unroll
                for (int ni = 0; ni < 4; ni++)
                    mma_bf16(acc[mi][ni], Al[mi], &Bh2[ni >> 1][(ni & 1) * 2]);
            #pragma unroll
            for (int mi = 0; mi < 4; mi++)
                #pragma unroll
                for (int ni = 0; ni < 4; ni++)
                    mma_bf16(acc[mi][ni], Ah[mi], &Bl2[ni >> 1][(ni & 1) * 2]);
        }
        __syncthreads();
        if (c + 1 < NCH) {
            store_smem(1 - cur);
            __syncthreads();
        }
    }

    // ---- epilogue ----
    const int gr = lane >> 2, gc = (lane & 3) * 2;
    #pragma unroll
    for (int mi = 0; mi < 4; mi++) {
        #pragma unroll
        for (int h = 0; h < 2; h++) {
            int row = m0 + wr * 64 + mi * 16 + gr + h * 8;
            size_t roff = (size_t)row * ldC;
            #pragma unroll
            for (int ni = 0; ni < 4; ni++) {
                int col = n0 + wc * 32 + ni * 8 + gc;
                if (col >= Nact) continue;
                float v0 = acc[mi][ni][h * 2];
                float v1 = acc[mi][ni][h * 2 + 1];
                if (EPI == 1 || EPI == 2) { v0 += bias[col]; v1 += bias[col + 1]; }
                if (EPI == 2) {
                    float u0 = 0.7978845608028654f * (v0 + 0.044715f * v0 * v0 * v0);
                    v0 = 0.5f * v0 * (1.0f + tanhf(u0));
                    float u1 = 0.7978845608028654f * (v1 + 0.044715f * v1 * v1 * v1);
                    v1 = 0.5f * v1 * (1.0f + tanhf(u1));
                }
                if (EPI == 3) {
                    v0 += res[roff + col];
                    v1 += res[roff + col + 1];
                }
                *reinterpret_cast<float2*>(C + roff + col) = make_float2(v0, v1);
            }
        }
    }
}

// ---------------------------------------------------------------------------
// Attention: one warp per (bs, head); RMSNorm + RoPE + 16x16 softmax.
// ---------------------------------------------------------------------------
__global__ __launch_bounds__(128)
void attn_kernel(const float* __restrict__ q_gamma,
                 const float* __restrict__ k_gamma)
{
    __shared__ float qs[4][TT][33];
    __shared__ float ks[4][TT][33];
    __shared__ float vs[4][TT][32];
    __shared__ float ps[4][TT][17];

    int warp = threadIdx.x >> 5;
    int lane = threadIdx.x & 31;
    int gw = blockIdx.x * 4 + warp;
    int head = gw % HEADS;
    int bs   = gw / HEADS;
    int b_idx = bs / S_SP;
    int s     = bs % S_SP;

    float q[TT], k[TT], v[TT];
    #pragma unroll
    for (int t = 0; t < TT; t++) {
        size_t base = ((size_t)(bs * TT + t)) * (3 * CDIM) + head * HDIM + lane;
        q[t] = g_qkv[base];
        k[t] = g_qkv[base + CDIM];
        v[t] = g_qkv[base + 2 * CDIM];
    }

    float qg = q_gamma[lane], kg = k_gamma[lane];
    float freq = 0.0f;
    if (lane < 24) {
        int p = lane >> 1;
        freq = exp2f(-8.0f * (float)(2 * p) / 24.0f);
    }

    #pragma unroll
    for (int t = 0; t < TT; t++) {
        float sq = q[t] * q[t];
        float sk = k[t] * k[t];
        #pragma unroll
        for (int o = 16; o > 0; o >>= 1) {
            sq += __shfl_xor_sync(0xffffffffu, sq, o);
            sk += __shfl_xor_sync(0xffffffffu, sk, o);
        }
        float qn = q[t] * rsqrtf(sq * (1.0f / 32.0f) + 1e-6f) * qg;
        float kn = k[t] * rsqrtf(sk * (1.0f / 32.0f) + 1e-6f) * kg;

        float c = 1.0f, sn = 0.0f;
        if (lane < 24) {
            float ang = freq * (float)t;
            c = cosf(ang);
            sn = sinf(ang);
        }
        float qr = __shfl_xor_sync(0xffffffffu, qn, 1);
        float kr = __shfl_xor_sync(0xffffffffu, kn, 1);
        qr = (lane & 1) ? qr : -qr;
        kr = (lane & 1) ? kr : -kr;

        qs[warp][t][lane] = qn * c + qr * sn;
        ks[warp][t][lane] = kn * c + kr * sn;
        vs[warp][t][lane] = v[t];
    }
    __syncwarp();

    const float scale = 0.17677669529663687f;
    #pragma unroll
    for (int i = 0; i < 8; i++) {
        int idx = lane * 8 + i;
        int t = idx >> 4, m = idx & 15;
        float sum = 0.0f;
        #pragma unroll
        for (int d = 0; d < HDIM; d++)
            sum = fmaf(qs[warp][t][d], ks[warp][m][d], sum);
        ps[warp][t][m] = sum * scale;
    }
    __syncwarp();

    if (lane < 16) {
        float mx = -1e30f;
        #pragma unroll
        for (int m = 0; m < 16; m++) mx = fmaxf(mx, ps[warp][lane][m]);
        float sum = 0.0f;
        #pragma unroll
        for (int m = 0; m < 16; m++) {
            float e = expf(ps[warp][lane][m] - mx);
            ps[warp][lane][m] = e;
            sum += e;
        }
        float inv = 1.0f / sum;
        #pragma unroll
        for (int m = 0; m < 16; m++) ps[warp][lane][m] *= inv;
    }
    __syncwarp();

    #pragma unroll
    for (int t = 0; t < TT; t++) {
        float o = 0.0f;
        #pragma unroll
        for (int m = 0; m < 16; m++)
            o = fmaf(ps[warp][t][m], vs[warp][m][lane], o);
        size_t orow = (size_t)b_idx * (TT * S_SP) + (size_t)t * S_SP + s;
        g_attn[orow * CDIM + head * HDIM + lane] = o;
    }
}

// ---------------------------------------------------------------------------
extern "C" void kernel_launch(void* const* d_in, const int* in_sizes, int n_in,
                              void* d_out, int out_size)
{
    const float* mouse = (const float*)d_in[0];
    const float* x     = (const float*)d_in[2];
    const float* w1    = (const float*)d_in[3];
    const float* b1    = (const float*)d_in[4];
    const float* w2    = (const float*)d_in[5];
    const float* b2    = (const float*)d_in[6];
    const float* qkvw  = (const float*)d_in[7];
    const float* qg    = (const float*)d_in[8];
    const float* kg    = (const float*)d_in[9];
    const float* pw    = (const float*)d_in[10];
    float* out = (float*)d_out;

    cudaFuncSetAttribute(mma_gemm<0>, cudaFuncAttributeMaxDynamicSharedMemorySize, SMEM_SZ);
    cudaFuncSetAttribute(mma_gemm<1>, cudaFuncAttributeMaxDynamicSharedMemorySize, SMEM_SZ);
    cudaFuncSetAttribute(mma_gemm<2>, cudaFuncAttributeMaxDynamicSharedMemorySize, SMEM_SZ);
    cudaFuncSetAttribute(mma_gemm<3>, cudaFuncAttributeMaxDynamicSharedMemorySize, SMEM_SZ);

    __nv_bfloat16 *w1h, *w1l, *w2h, *w2l, *w3h, *w3l, *w4h, *w4l;
    cudaGetSymbolAddress((void**)&w1h, g_w1h); cudaGetSymbolAddress((void**)&w1l, g_w1l);
    cudaGetSymbolAddress((void**)&w2h, g_w2h); cudaGetSymbolAddress((void**)&w2l, g_w2l);
    cudaGetSymbolAddress((void**)&w3h, g_w3h); cudaGetSymbolAddress((void**)&w3l, g_w3l);
    cudaGetSymbolAddress((void**)&w4h, g_w4h); cudaGetSymbolAddress((void**)&w4l, g_w4l);

    dim3 cb(32, 8);
    conv_weight<<<dim3(1024/32, 832/32), cb>>>(w1,   w1h, w1l, 792, 792,  832);
    conv_weight<<<dim3( 768/32, 832/32), cb>>>(w2,   w2h, w2l, 792, 768,  832);
    conv_weight<<<dim3(2304/32, 768/32), cb>>>(qkvw, w3h, w3l, 768, 2304, 768);
    conv_weight<<<dim3( 768/32, 768/32), cb>>>(pw,   w4h, w4l, 768, 768,  768);

    build_z_kernel<<<NROWS, 128>>>(x, mouse);

    float *zP, *hP, *fP, *qkvP, *attnP;
    cudaGetSymbolAddress((void**)&zP, g_z);
    cudaGetSymbolAddress((void**)&hP, g_h);
    cudaGetSymbolAddress((void**)&fP, g_feat);
    cudaGetSymbolAddress((void**)&qkvP, g_qkv);
    cudaGetSymbolAddress((void**)&attnP, g_attn);

    // h = gelu(z @ w1 + b1)   N=792 (7 tiles), K=792 (Kpad 832)
    mma_gemm<2><<<dim3(7, NROWS/128), 256, SMEM_SZ>>>(
        zP, w1h, w1l, b1, nullptr, hP, 792, 792, 832, INMLP, INMLP);
    // feat = h @ w2 + b2      N=768, K=792
    mma_gemm<1><<<dim3(6, NROWS/128), 256, SMEM_SZ>>>(
        hP, w2h, w2l, b2, nullptr, fP, 768, 792, 832, INMLP, CDIM);
    // qkv = feat @ qkv_w      N=2304, K=768
    mma_gemm<0><<<dim3(18, NROWS/128), 256, SMEM_SZ>>>(
        fP, w3h, w3l, nullptr, nullptr, qkvP, 2304, 768, 768, CDIM, 3*CDIM);

    attn_kernel<<<(BATCH * S_SP * HEADS) / 4, 128>>>(qg, kg);

    // out = x + attn @ proj_w  N=768, K=768
    mma_gemm<3><<<dim3(6, NROWS/128), 256, SMEM_SZ>>>(
        attnP, w4h, w4l, nullptr, x, out, 768, 768, 768, CDIM, CDIM);

    (void)in_sizes; (void)n_in; (void)out_size;
}

// round 9
// speedup vs baseline: 2.5975x; 1.0852x over previous
#include <cuda_runtime.h>
#include <cuda_bf16.h>
#include <math.h>
#include <stdint.h>

// Problem constants (fixed by setup_inputs)
#define HEADS  24
#define HDIM   32
#define TT     16
#define S_SP   1560            // th*tw
#define BATCH  2
#define CDIM   768
#define INMLP  792
#define NROWS  (BATCH*S_SP*TT) // 49920
#define NF     61
#define PADT   12
#define KP1    832             // padded K for layer1/2 inputs

// ---------------------------------------------------------------------------
// Scratch (static device globals; no runtime allocation)
// All intermediates stored as hi/lo bf16 planes (≈fp32 accuracy, half traffic)
// ---------------------------------------------------------------------------
__device__ __nv_bfloat16 g_zh[(size_t)NROWS * KP1];
__device__ __nv_bfloat16 g_zl[(size_t)NROWS * KP1];
__device__ __nv_bfloat16 g_hh[(size_t)NROWS * KP1];
__device__ __nv_bfloat16 g_hl[(size_t)NROWS * KP1];
__device__ __nv_bfloat16 g_fh[(size_t)NROWS * CDIM];
__device__ __nv_bfloat16 g_fl[(size_t)NROWS * CDIM];
__device__ __nv_bfloat16 g_ath[(size_t)NROWS * CDIM];
__device__ __nv_bfloat16 g_atl[(size_t)NROWS * CDIM];
__device__ float g_qkv[(size_t)NROWS * 3 * CDIM];

// Pre-transposed, hi/lo-split weights: [Npad][Kpad] bf16, K contiguous
__device__ __nv_bfloat16 g_w1h[(size_t)1024 * KP1];
__device__ __nv_bfloat16 g_w1l[(size_t)1024 * KP1];
__device__ __nv_bfloat16 g_w2h[(size_t)768  * KP1];
__device__ __nv_bfloat16 g_w2l[(size_t)768  * KP1];
__device__ __nv_bfloat16 g_w3h[(size_t)2304 * 768];
__device__ __nv_bfloat16 g_w3l[(size_t)2304 * 768];
__device__ __nv_bfloat16 g_w4h[(size_t)768  * 768];
__device__ __nv_bfloat16 g_w4l[(size_t)768  * 768];

// ---------------------------------------------------------------------------
// helpers
// ---------------------------------------------------------------------------
__device__ __forceinline__ uint32_t s2u(const void* p) {
    uint32_t a;
    asm("{ .reg .u64 t; cvta.to.shared.u64 t, %1; cvt.u32.u64 %0, t; }"
        : "=r"(a) : "l"(p));
    return a;
}

__device__ __forceinline__ void ldsm4(uint32_t* r, uint32_t a) {
    asm volatile("ldmatrix.sync.aligned.m8n8.x4.shared.b16 {%0,%1,%2,%3}, [%4];"
        : "=r"(r[0]), "=r"(r[1]), "=r"(r[2]), "=r"(r[3]) : "r"(a));
}

__device__ __forceinline__ void mma_bf16(float* d, const uint32_t* a,
                                         const uint32_t* b) {
    asm volatile(
        "mma.sync.aligned.m16n8k16.row.col.f32.bf16.bf16.f32 "
        "{%0,%1,%2,%3}, {%4,%5,%6,%7}, {%8,%9}, {%0,%1,%2,%3};"
        : "+f"(d[0]), "+f"(d[1]), "+f"(d[2]), "+f"(d[3])
        : "r"(a[0]), "r"(a[1]), "r"(a[2]), "r"(a[3]), "r"(b[0]), "r"(b[1]));
}

__device__ __forceinline__ void cp16(uint32_t dst, const void* src) {
    asm volatile("cp.async.cg.shared.global [%0], [%1], 16;"
                 :: "r"(dst), "l"(src) : "memory");
}

__device__ __forceinline__ uint32_t pack_bf(float e0, float e1) {
    uint32_t r;
    asm("cvt.rn.bf16x2.f32 %0, %1, %2;" : "=r"(r) : "f"(e1), "f"(e0));
    return r;
}

// split v into hi/lo bf16
__device__ __forceinline__ void split_bf(float v, __nv_bfloat16& h,
                                         __nv_bfloat16& l) {
    h = __float2bfloat16(v);
    l = __float2bfloat16(v - __bfloat162float(h));
}

// ---------------------------------------------------------------------------
// Weight transpose + hi/lo split: W(K x N fp32) -> [Npad][Kpad] bf16
// ---------------------------------------------------------------------------
__global__ void conv_weight(const float* __restrict__ W,
                            __nv_bfloat16* __restrict__ hi,
                            __nv_bfloat16* __restrict__ lo,
                            int K, int N, int Kpad) {
    __shared__ float t[32][33];
    int n0 = blockIdx.x * 32, k0 = blockIdx.y * 32;
    int tx = threadIdx.x, ty = threadIdx.y;  // 32 x 8
    #pragma unroll
    for (int j = 0; j < 32; j += 8) {
        int k = k0 + ty + j, n = n0 + tx;
        t[ty + j][tx] = (k < K && n < N) ? W[(size_t)k * N + n] : 0.0f;
    }
    __syncthreads();
    #pragma unroll
    for (int j = 0; j < 32; j += 8) {
        int n = n0 + ty + j, k = k0 + tx;
        float v = t[tx][ty + j];
        __nv_bfloat16 h, l;
        split_bf(v, h, l);
        hi[(size_t)n * Kpad + k] = h;
        lo[(size_t)n * Kpad + k] = l;
    }
}

// ---------------------------------------------------------------------------
// build z (hi/lo split) = concat(x_row, gathered mouse, zero pad to 832)
// ---------------------------------------------------------------------------
__global__ void build_z_kernel(const float* __restrict__ x,
                               const float* __restrict__ mouse) {
    int r = blockIdx.x;
    int bs = r / TT, t = r % TT;
    int b_idx = bs / S_SP, s = bs % S_SP;

    const float* xr = x + ((size_t)b_idx * (TT * S_SP) + (size_t)t * S_SP + s) * CDIM;
    __nv_bfloat16* zh = g_zh + (size_t)r * KP1;
    __nv_bfloat16* zl = g_zl + (size_t)r * KP1;

    for (int g = threadIdx.x; g < CDIM / 4; g += blockDim.x) {
        float4 v = reinterpret_cast<const float4*>(xr)[g];
        __nv_bfloat16 h0, l0, h1, l1, h2, l2, h3, l3;
        split_bf(v.x, h0, l0); split_bf(v.y, h1, l1);
        split_bf(v.z, h2, l2); split_bf(v.w, h3, l3);
        uint32_t hA = ((uint32_t)__bfloat16_as_ushort(h1) << 16) | __bfloat16_as_ushort(h0);
        uint32_t hB = ((uint32_t)__bfloat16_as_ushort(h3) << 16) | __bfloat16_as_ushort(h2);
        uint32_t lA = ((uint32_t)__bfloat16_as_ushort(l1) << 16) | __bfloat16_as_ushort(l0);
        uint32_t lB = ((uint32_t)__bfloat16_as_ushort(l3) << 16) | __bfloat16_as_ushort(l2);
        reinterpret_cast<uint2*>(zh)[g] = make_uint2(hA, hB);
        reinterpret_cast<uint2*>(zl)[g] = make_uint2(lA, lB);
    }

    if (threadIdx.x < 64) {
        int col = CDIM + threadIdx.x;    // 768..831
        float v = 0.0f;
        if (col < INMLP) {
            int j  = (col - CDIM) >> 1;
            int ch = (col - CDIM) & 1;
            int i  = 4 * t + j;
            if (i >= PADT) v = mouse[((size_t)b_idx * NF + (i - PADT)) * 2 + ch];
        }
        __nv_bfloat16 h, l;
        split_bf(v, h, l);
        zh[col] = h;
        zl[col] = l;
    }
}

// ---------------------------------------------------------------------------
// bf16 split GEMM on HMMA, cp.async 4-stage pipeline.
// A/B both pre-split hi/lo bf16 in global, [rows][Kpad] K-contiguous.
// CTA 128x128, BK=32, 8 warps (2x4), warp tile 64x32.
// 3 passes: Ah*Bh + Al*Bh + Ah*Bl.
// EPI: 0 none, 1 +bias, 2 +bias+gelu, 3 +residual
// SPLITOUT: 1 -> write hi/lo bf16 planes (ldC stride), 0 -> fp32 C
// ---------------------------------------------------------------------------
#define OFF_AH 0
#define OFF_AL 8192
#define OFF_BH 16384
#define OFF_BL 24576
#define STAGE  32768
#define NSTAGE 4
#define SMEM_SZ (NSTAGE*STAGE)

template<int EPI, int SPLITOUT>
__global__ void __launch_bounds__(256, 1)
mma_gemm(const __nv_bfloat16* __restrict__ Ah_g,
         const __nv_bfloat16* __restrict__ Al_g,
         const __nv_bfloat16* __restrict__ Bh_g,
         const __nv_bfloat16* __restrict__ Bl_g,
         const float* __restrict__ bias,
         const float* __restrict__ res,
         float* __restrict__ C,
         __nv_bfloat16* __restrict__ Ch,
         __nv_bfloat16* __restrict__ Cl,
         int Nact, int Nstore, int Kpad, int ldC)
{
    extern __shared__ char smem[];
    const uint32_t sb = s2u(smem);
    const int tid = threadIdx.x, wid = tid >> 5, lane = tid & 31;
    const int m0 = blockIdx.y * 128, n0 = blockIdx.x * 128;
    const int wr = wid & 1, wc = wid >> 1;
    const int NCH = Kpad >> 5;

    // two load entries per thread per plane: e = tid, tid+256; r=e>>2, sg=e&3
    const int r0 = tid >> 2,        sg0 = tid & 3;
    const int r1 = (tid + 256) >> 2, sg1 = (tid + 256) & 3;
    const uint32_t off0 = (uint32_t)(r0 * 64 + ((sg0 ^ ((r0 >> 1) & 3)) << 4));
    const uint32_t off1 = (uint32_t)(r1 * 64 + ((sg1 ^ ((r1 >> 1) & 3)) << 4));
    const size_t ga0 = (size_t)(m0 + r0) * Kpad + sg0 * 8;
    const size_t ga1 = (size_t)(m0 + r1) * Kpad + sg1 * 8;
    const size_t gb0 = (size_t)(n0 + r0) * Kpad + sg0 * 8;
    const size_t gb1 = (size_t)(n0 + r1) * Kpad + sg1 * 8;

    auto issue = [&](int c) {
        if (c < NCH) {
            const uint32_t st = sb + (uint32_t)(c & (NSTAGE - 1)) * STAGE;
            const int k0 = c * 32;
            cp16(st + OFF_AH + off0, Ah_g + ga0 + k0);
            cp16(st + OFF_AH + off1, Ah_g + ga1 + k0);
            cp16(st + OFF_AL + off0, Al_g + ga0 + k0);
            cp16(st + OFF_AL + off1, Al_g + ga1 + k0);
            cp16(st + OFF_BH + off0, Bh_g + gb0 + k0);
            cp16(st + OFF_BH + off1, Bh_g + gb1 + k0);
            cp16(st + OFF_BL + off0, Bl_g + gb0 + k0);
            cp16(st + OFF_BL + off1, Bl_g + gb1 + k0);
        }
        asm volatile("cp.async.commit_group;" ::: "memory");
    };

    issue(0); issue(1); issue(2);

    float acc[4][4][4] = {};

    const int a_r = lane & 15;
    const int a_s = lane >> 4;
    const int b_n = (lane & 7) + ((lane >> 4) << 3);
    const int b_s = (lane >> 3) & 1;

    for (int c = 0; c < NCH; c++) {
        asm volatile("cp.async.wait_group %0;" :: "n"(NSTAGE - 2) : "memory");
        __syncthreads();
        issue(c + NSTAGE - 1);

        const uint32_t st = sb + (uint32_t)(c & (NSTAGE - 1)) * STAGE;
        #pragma unroll
        for (int step = 0; step < 2; step++) {
            uint32_t Ahr[4][4], Alr[4][4], Bh2[2][4], Bl2[2][4];
            #pragma unroll
            for (int mi = 0; mi < 4; mi++) {
                int row = wr * 64 + mi * 16 + a_r;
                int ks = step * 2 + a_s;
                uint32_t off = (uint32_t)(row * 64 +
                               ((ks ^ ((row >> 1) & 3)) << 4));
                ldsm4(Ahr[mi], st + OFF_AH + off);
                ldsm4(Alr[mi], st + OFF_AL + off);
            }
            #pragma unroll
            for (int np = 0; np < 2; np++) {
                int row = wc * 32 + np * 16 + b_n;
                int ks = step * 2 + b_s;
                uint32_t off = (uint32_t)(row * 64 +
                               ((ks ^ ((row >> 1) & 3)) << 4));
                ldsm4(Bh2[np], st + OFF_BH + off);
                ldsm4(Bl2[np], st + OFF_BL + off);
            }
            #pragma unroll
            for (int mi = 0; mi < 4; mi++)
                #pragma unroll
                for (int ni = 0; ni < 4; ni++)
                    mma_bf16(acc[mi][ni], Ahr[mi], &Bh2[ni >> 1][(ni & 1) * 2]);
            #pragma unroll
            for (int mi = 0; mi < 4; mi++)
                #pragma unroll
                for (int ni = 0; ni < 4; ni++)
                    mma_bf16(acc[mi][ni], Alr[mi], &Bh2[ni >> 1][(ni & 1) * 2]);
            #pragma unroll
            for (int mi = 0; mi < 4; mi++)
                #pragma unroll
                for (int ni = 0; ni < 4; ni++)
                    mma_bf16(acc[mi][ni], Ahr[mi], &Bl2[ni >> 1][(ni & 1) * 2]);
        }
        __syncthreads();
    }

    // ---- epilogue ----
    const int gr = lane >> 2, gc = (lane & 3) * 2;
    #pragma unroll
    for (int mi = 0; mi < 4; mi++) {
        #pragma unroll
        for (int h = 0; h < 2; h++) {
            int row = m0 + wr * 64 + mi * 16 + gr + h * 8;
            size_t roff = (size_t)row * ldC;
            #pragma unroll
            for (int ni = 0; ni < 4; ni++) {
                int col = n0 + wc * 32 + ni * 8 + gc;
                if (SPLITOUT) {
                    if (col >= Nstore) continue;
                } else {
                    if (col >= Nact) continue;
                }
                float v0 = acc[mi][ni][h * 2];
                float v1 = acc[mi][ni][h * 2 + 1];
                if (SPLITOUT && col >= Nact) { v0 = 0.f; v1 = 0.f; }
                else {
                    if (EPI == 1 || EPI == 2) { v0 += bias[col]; v1 += bias[col + 1]; }
                    if (EPI == 2) {
                        float u0 = 0.7978845608028654f * (v0 + 0.044715f * v0 * v0 * v0);
                        v0 = 0.5f * v0 * (1.0f + tanhf(u0));
                        float u1 = 0.7978845608028654f * (v1 + 0.044715f * v1 * v1 * v1);
                        v1 = 0.5f * v1 * (1.0f + tanhf(u1));
                    }
                    if (EPI == 3) {
                        v0 += res[roff + col];
                        v1 += res[roff + col + 1];
                    }
                }
                if (SPLITOUT) {
                    __nv_bfloat16 h0, l0, h1, l1;
                    split_bf(v0, h0, l0);
                    split_bf(v1, h1, l1);
                    *reinterpret_cast<uint32_t*>(Ch + roff + col) =
                        ((uint32_t)__bfloat16_as_ushort(h1) << 16) | __bfloat16_as_ushort(h0);
                    *reinterpret_cast<uint32_t*>(Cl + roff + col) =
                        ((uint32_t)__bfloat16_as_ushort(l1) << 16) | __bfloat16_as_ushort(l0);
                } else {
                    *reinterpret_cast<float2*>(C + roff + col) = make_float2(v0, v1);
                }
            }
        }
    }
}

// ---------------------------------------------------------------------------
// Attention: one warp per (bs, head); RMSNorm + RoPE + 16x16 softmax.
// Output written as hi/lo bf16 planes for the proj GEMM.
// ---------------------------------------------------------------------------
__global__ __launch_bounds__(128)
void attn_kernel(const float* __restrict__ q_gamma,
                 const float* __restrict__ k_gamma)
{
    __shared__ float qs[4][TT][33];
    __shared__ float ks[4][TT][33];
    __shared__ float vs[4][TT][32];
    __shared__ float ps[4][TT][17];

    int warp = threadIdx.x >> 5;
    int lane = threadIdx.x & 31;
    int gw = blockIdx.x * 4 + warp;
    int head = gw % HEADS;
    int bs   = gw / HEADS;
    int b_idx = bs / S_SP;
    int s     = bs % S_SP;

    float q[TT], k[TT], v[TT];
    #pragma unroll
    for (int t = 0; t < TT; t++) {
        size_t base = ((size_t)(bs * TT + t)) * (3 * CDIM) + head * HDIM + lane;
        q[t] = g_qkv[base];
        k[t] = g_qkv[base + CDIM];
        v[t] = g_qkv[base + 2 * CDIM];
    }

    float qg = q_gamma[lane], kg = k_gamma[lane];
    float freq = 0.0f;
    if (lane < 24) {
        int p = lane >> 1;
        freq = exp2f(-8.0f * (float)(2 * p) / 24.0f);
    }

    #pragma unroll
    for (int t = 0; t < TT; t++) {
        float sq = q[t] * q[t];
        float sk = k[t] * k[t];
        #pragma unroll
        for (int o = 16; o > 0; o >>= 1) {
            sq += __shfl_xor_sync(0xffffffffu, sq, o);
            sk += __shfl_xor_sync(0xffffffffu, sk, o);
        }
        float qn = q[t] * rsqrtf(sq * (1.0f / 32.0f) + 1e-6f) * qg;
        float kn = k[t] * rsqrtf(sk * (1.0f / 32.0f) + 1e-6f) * kg;

        float c = 1.0f, sn = 0.0f;
        if (lane < 24) {
            float ang = freq * (float)t;
            c = cosf(ang);
            sn = sinf(ang);
        }
        float qr = __shfl_xor_sync(0xffffffffu, qn, 1);
        float kr = __shfl_xor_sync(0xffffffffu, kn, 1);
        qr = (lane & 1) ? qr : -qr;
        kr = (lane & 1) ? kr : -kr;

        qs[warp][t][lane] = qn * c + qr * sn;
        ks[warp][t][lane] = kn * c + kr * sn;
        vs[warp][t][lane] = v[t];
    }
    __syncwarp();

    const float scale = 0.17677669529663687f;
    #pragma unroll
    for (int i = 0; i < 8; i++) {
        int idx = lane * 8 + i;
        int t = idx >> 4, m = idx & 15;
        float sum = 0.0f;
        #pragma unroll
        for (int d = 0; d < HDIM; d++)
            sum = fmaf(qs[warp][t][d], ks[warp][m][d], sum);
        ps[warp][t][m] = sum * scale;
    }
    __syncwarp();

    if (lane < 16) {
        float mx = -1e30f;
        #pragma unroll
        for (int m = 0; m < 16; m++) mx = fmaxf(mx, ps[warp][lane][m]);
        float sum = 0.0f;
        #pragma unroll
        for (int m = 0; m < 16; m++) {
            float e = expf(ps[warp][lane][m] - mx);
            ps[warp][lane][m] = e;
            sum += e;
        }
        float inv = 1.0f / sum;
        #pragma unroll
        for (int m = 0; m < 16; m++) ps[warp][lane][m] *= inv;
    }
    __syncwarp();

    #pragma unroll
    for (int t = 0; t < TT; t++) {
        float o = 0.0f;
        #pragma unroll
        for (int m = 0; m < 16; m++)
            o = fmaf(ps[warp][t][m], vs[warp][m][lane], o);
        size_t orow = (size_t)b_idx * (TT * S_SP) + (size_t)t * S_SP + s;
        __nv_bfloat16 h, l;
        split_bf(o, h, l);
        g_ath[orow * CDIM + head * HDIM + lane] = h;
        g_atl[orow * CDIM + head * HDIM + lane] = l;
    }
}

// ---------------------------------------------------------------------------
extern "C" void kernel_launch(void* const* d_in, const int* in_sizes, int n_in,
                              void* d_out, int out_size)
{
    const float* mouse = (const float*)d_in[0];
    const float* x     = (const float*)d_in[2];
    const float* w1    = (const float*)d_in[3];
    const float* b1    = (const float*)d_in[4];
    const float* w2    = (const float*)d_in[5];
    const float* b2    = (const float*)d_in[6];
    const float* qkvw  = (const float*)d_in[7];
    const float* qg    = (const float*)d_in[8];
    const float* kg    = (const float*)d_in[9];
    const float* pw    = (const float*)d_in[10];
    float* out = (float*)d_out;

    cudaFuncSetAttribute(mma_gemm<2,1>, cudaFuncAttributeMaxDynamicSharedMemorySize, SMEM_SZ);
    cudaFuncSetAttribute(mma_gemm<1,1>, cudaFuncAttributeMaxDynamicSharedMemorySize, SMEM_SZ);
    cudaFuncSetAttribute(mma_gemm<0,0>, cudaFuncAttributeMaxDynamicSharedMemorySize, SMEM_SZ);
    cudaFuncSetAttribute(mma_gemm<3,0>, cudaFuncAttributeMaxDynamicSharedMemorySize, SMEM_SZ);

    __nv_bfloat16 *w1h, *w1l, *w2h, *w2l, *w3h, *w3l, *w4h, *w4l;
    cudaGetSymbolAddress((void**)&w1h, g_w1h); cudaGetSymbolAddress((void**)&w1l, g_w1l);
    cudaGetSymbolAddress((void**)&w2h, g_w2h); cudaGetSymbolAddress((void**)&w2l, g_w2l);
    cudaGetSymbolAddress((void**)&w3h, g_w3h); cudaGetSymbolAddress((void**)&w3l, g_w3l);
    cudaGetSymbolAddress((void**)&w4h, g_w4h); cudaGetSymbolAddress((void**)&w4l, g_w4l);

    __nv_bfloat16 *zh, *zl, *hh, *hl, *fh, *fl, *ath, *atl;
    cudaGetSymbolAddress((void**)&zh, g_zh);  cudaGetSymbolAddress((void**)&zl, g_zl);
    cudaGetSymbolAddress((void**)&hh, g_hh);  cudaGetSymbolAddress((void**)&hl, g_hl);
    cudaGetSymbolAddress((void**)&fh, g_fh);  cudaGetSymbolAddress((void**)&fl, g_fl);
    cudaGetSymbolAddress((void**)&ath, g_ath); cudaGetSymbolAddress((void**)&atl, g_atl);
    float* qkvP;
    cudaGetSymbolAddress((void**)&qkvP, g_qkv);

    dim3 cb(32, 8);
    conv_weight<<<dim3(1024/32, KP1/32), cb>>>(w1,   w1h, w1l, 792, 792,  KP1);
    conv_weight<<<dim3( 768/32, KP1/32), cb>>>(w2,   w2h, w2l, 792, 768,  KP1);
    conv_weight<<<dim3(2304/32, 768/32), cb>>>(qkvw, w3h, w3l, 768, 2304, 768);
    conv_weight<<<dim3( 768/32, 768/32), cb>>>(pw,   w4h, w4l, 768, 768,  768);

    build_z_kernel<<<NROWS, 128>>>(x, mouse);

    // h = gelu(z @ w1 + b1) -> split   N=792 (7 tiles), Nstore=832, K=832
    mma_gemm<2,1><<<dim3(7, NROWS/128), 256, SMEM_SZ>>>(
        zh, zl, w1h, w1l, b1, nullptr, nullptr, hh, hl, 792, KP1, KP1, KP1);
    // feat = h @ w2 + b2 -> split      N=768, K=832
    mma_gemm<1,1><<<dim3(6, NROWS/128), 256, SMEM_SZ>>>(
        hh, hl, w2h, w2l, b2, nullptr, nullptr, fh, fl, 768, 768, KP1, CDIM);
    // qkv = feat @ qkv_w -> fp32       N=2304, K=768
    mma_gemm<0,0><<<dim3(18, NROWS/128), 256, SMEM_SZ>>>(
        fh, fl, w3h, w3l, nullptr, nullptr, qkvP, nullptr, nullptr,
        2304, 2304, 768, 3*CDIM);

    attn_kernel<<<(BATCH * S_SP * HEADS) / 4, 128>>>(qg, kg);

    // out = x + attn @ proj_w -> fp32  N=768, K=768
    mma_gemm<3,0><<<dim3(6, NROWS/128), 256, SMEM_SZ>>>(
        ath, atl, w4h, w4l, nullptr, x, out, nullptr, nullptr,
        768, 768, 768, CDIM);

    (void)in_sizes; (void)n_in; (void)out_size;
}

// round 10
// speedup vs baseline: 3.4943x; 1.3453x over previous
#include <cuda_runtime.h>
#include <cuda_fp16.h>
#include <math.h>
#include <stdint.h>

// Problem constants (fixed by setup_inputs)
#define HEADS  24
#define HDIM   32
#define TT     16
#define S_SP   1560            // th*tw
#define BATCH  2
#define CDIM   768
#define INMLP  792
#define NROWS  (BATCH*S_SP*TT) // 49920
#define NF     61
#define PADT   12
#define KP1    832             // padded K for layer1/2 inputs

// ---------------------------------------------------------------------------
// Scratch (static device globals; no runtime allocation)
// Activations stored as hi/lo fp16 planes (~22 mantissa bits);
// weights stored as single fp16 plane (error u=2^-11, attenuated in dot prods)
// ---------------------------------------------------------------------------
__device__ __half g_zh[(size_t)NROWS * KP1];
__device__ __half g_zl[(size_t)NROWS * KP1];
__device__ __half g_hh[(size_t)NROWS * KP1];
__device__ __half g_hl[(size_t)NROWS * KP1];
__device__ __half g_fh[(size_t)NROWS * CDIM];
__device__ __half g_fl[(size_t)NROWS * CDIM];
__device__ __half g_ath[(size_t)NROWS * CDIM];
__device__ __half g_atl[(size_t)NROWS * CDIM];
__device__ float g_qkv[(size_t)NROWS * 3 * CDIM];

// Pre-transposed fp16 weights: [Npad][Kpad], K contiguous
__device__ __half g_w1[(size_t)1024 * KP1];
__device__ __half g_w2[(size_t)768  * KP1];
__device__ __half g_w3[(size_t)2304 * 768];
__device__ __half g_w4[(size_t)768  * 768];

// ---------------------------------------------------------------------------
// helpers
// ---------------------------------------------------------------------------
__device__ __forceinline__ uint32_t s2u(const void* p) {
    uint32_t a;
    asm("{ .reg .u64 t; cvta.to.shared.u64 t, %1; cvt.u32.u64 %0, t; }"
        : "=r"(a) : "l"(p));
    return a;
}

__device__ __forceinline__ void ldsm4(uint32_t* r, uint32_t a) {
    asm volatile("ldmatrix.sync.aligned.m8n8.x4.shared.b16 {%0,%1,%2,%3}, [%4];"
        : "=r"(r[0]), "=r"(r[1]), "=r"(r[2]), "=r"(r[3]) : "r"(a));
}

__device__ __forceinline__ void mma_f16(float* d, const uint32_t* a,
                                        const uint32_t* b) {
    asm volatile(
        "mma.sync.aligned.m16n8k16.row.col.f32.f16.f16.f32 "
        "{%0,%1,%2,%3}, {%4,%5,%6,%7}, {%8,%9}, {%0,%1,%2,%3};"
        : "+f"(d[0]), "+f"(d[1]), "+f"(d[2]), "+f"(d[3])
        : "r"(a[0]), "r"(a[1]), "r"(a[2]), "r"(a[3]), "r"(b[0]), "r"(b[1]));
}

__device__ __forceinline__ void cp16(uint32_t dst, const void* src) {
    asm volatile("cp.async.cg.shared.global [%0], [%1], 16;"
                 :: "r"(dst), "l"(src) : "memory");
}

// split v into hi/lo fp16
__device__ __forceinline__ void split_h(float v, __half& h, __half& l) {
    h = __float2half_rn(v);
    l = __float2half_rn(v - __half2float(h));
}

__device__ __forceinline__ uint32_t pack_h(__half a, __half b) {
    return ((uint32_t)__half_as_ushort(b) << 16) | __half_as_ushort(a);
}

// ---------------------------------------------------------------------------
// Weight transpose to fp16: W(K x N fp32) -> [Npad][Kpad] fp16
// ---------------------------------------------------------------------------
__global__ void conv_weight(const float* __restrict__ W,
                            __half* __restrict__ out,
                            int K, int N, int Kpad) {
    __shared__ float t[32][33];
    int n0 = blockIdx.x * 32, k0 = blockIdx.y * 32;
    int tx = threadIdx.x, ty = threadIdx.y;  // 32 x 8
    #pragma unroll
    for (int j = 0; j < 32; j += 8) {
        int k = k0 + ty + j, n = n0 + tx;
        t[ty + j][tx] = (k < K && n < N) ? W[(size_t)k * N + n] : 0.0f;
    }
    __syncthreads();
    #pragma unroll
    for (int j = 0; j < 32; j += 8) {
        int n = n0 + ty + j, k = k0 + tx;
        out[(size_t)n * Kpad + k] = __float2half_rn(t[tx][ty + j]);
    }
}

// ---------------------------------------------------------------------------
// build z (hi/lo fp16) = concat(x_row, gathered mouse, zero pad to 832)
// ---------------------------------------------------------------------------
__global__ void build_z_kernel(const float* __restrict__ x,
                               const float* __restrict__ mouse) {
    int r = blockIdx.x;
    int bs = r / TT, t = r % TT;
    int b_idx = bs / S_SP, s = bs % S_SP;

    const float* xr = x + ((size_t)b_idx * (TT * S_SP) + (size_t)t * S_SP + s) * CDIM;
    __half* zh = g_zh + (size_t)r * KP1;
    __half* zl = g_zl + (size_t)r * KP1;

    for (int g = threadIdx.x; g < CDIM / 4; g += blockDim.x) {
        float4 v = reinterpret_cast<const float4*>(xr)[g];
        __half h0, l0, h1, l1, h2, l2, h3, l3;
        split_h(v.x, h0, l0); split_h(v.y, h1, l1);
        split_h(v.z, h2, l2); split_h(v.w, h3, l3);
        reinterpret_cast<uint2*>(zh)[g] = make_uint2(pack_h(h0, h1), pack_h(h2, h3));
        reinterpret_cast<uint2*>(zl)[g] = make_uint2(pack_h(l0, l1), pack_h(l2, l3));
    }

    if (threadIdx.x < 64) {
        int col = CDIM + threadIdx.x;    // 768..831
        float v = 0.0f;
        if (col < INMLP) {
            int j  = (col - CDIM) >> 1;
            int ch = (col - CDIM) & 1;
            int i  = 4 * t + j;
            if (i >= PADT) v = mouse[((size_t)b_idx * NF + (i - PADT)) * 2 + ch];
        }
        __half h, l;
        split_h(v, h, l);
        zh[col] = h;
        zl[col] = l;
    }
}

// ---------------------------------------------------------------------------
// fp16 2-pass GEMM on HMMA, cp.async 4-stage pipeline.
// C = (Ah + Al) @ Bh  (error = A @ (B - Bh) ~ u_fp16, attenuated)
// CTA 128x128, 512 threads, 16 warps (4x4), warp tile 32x32, BK=32.
// EPI: 0 none, 1 +bias, 2 +bias+gelu, 3 +residual
// SPLITOUT: 1 -> write hi/lo fp16 planes, 0 -> fp32 C
// ---------------------------------------------------------------------------
#define OFF_AH 0
#define OFF_AL 8192
#define OFF_BH 16384
#define STAGE  24576
#define NSTAGE 4
#define SMEM_SZ (NSTAGE*STAGE)

template<int EPI, int SPLITOUT>
__global__ void __launch_bounds__(512, 1)
mma_gemm(const __half* __restrict__ Ah_g,
         const __half* __restrict__ Al_g,
         const __half* __restrict__ B_g,
         const float* __restrict__ bias,
         const float* __restrict__ res,
         float* __restrict__ C,
         __half* __restrict__ Ch,
         __half* __restrict__ Cl,
         int Nact, int Nstore, int Kpad, int ldC)
{
    extern __shared__ char smem[];
    const uint32_t sb = s2u(smem);
    const int tid = threadIdx.x, wid = tid >> 5, lane = tid & 31;
    const int m0 = blockIdx.y * 128, n0 = blockIdx.x * 128;
    const int wr = wid & 3, wc = wid >> 2;      // 4x4 warp grid
    const int NCH = Kpad >> 5;

    // one 16B segment per thread per plane (512 segs per 8KB plane)
    const int r0 = tid >> 2, sg0 = tid & 3;
    const uint32_t off0 = (uint32_t)(r0 * 64 + ((sg0 ^ ((r0 >> 1) & 3)) << 4));
    const size_t ga0 = (size_t)(m0 + r0) * Kpad + sg0 * 8;
    const size_t gb0 = (size_t)(n0 + r0) * Kpad + sg0 * 8;

    auto issue = [&](int c) {
        if (c < NCH) {
            const uint32_t st = sb + (uint32_t)(c & (NSTAGE - 1)) * STAGE;
            const int k0 = c * 32;
            cp16(st + OFF_AH + off0, Ah_g + ga0 + k0);
            cp16(st + OFF_AL + off0, Al_g + ga0 + k0);
            cp16(st + OFF_BH + off0, B_g  + gb0 + k0);
        }
        asm volatile("cp.async.commit_group;" ::: "memory");
    };

    issue(0); issue(1); issue(2);

    float acc[2][4][4] = {};

    const int a_r = lane & 15;
    const int a_s = lane >> 4;
    const int b_n = (lane & 7) + ((lane >> 4) << 3);
    const int b_s = (lane >> 3) & 1;

    for (int c = 0; c < NCH; c++) {
        asm volatile("cp.async.wait_group %0;" :: "n"(NSTAGE - 2) : "memory");
        __syncthreads();
        issue(c + NSTAGE - 1);

        const uint32_t st = sb + (uint32_t)(c & (NSTAGE - 1)) * STAGE;
        #pragma unroll
        for (int step = 0; step < 2; step++) {
            uint32_t Ahr[2][4], Alr[2][4], Bh2[2][4];
            #pragma unroll
            for (int mi = 0; mi < 2; mi++) {
                int row = wr * 32 + mi * 16 + a_r;
                int ks = step * 2 + a_s;
                uint32_t off = (uint32_t)(row * 64 +
                               ((ks ^ ((row >> 1) & 3)) << 4));
                ldsm4(Ahr[mi], st + OFF_AH + off);
                ldsm4(Alr[mi], st + OFF_AL + off);
            }
            #pragma unroll
            for (int np = 0; np < 2; np++) {
                int row = wc * 32 + np * 16 + b_n;
                int ks = step * 2 + b_s;
                uint32_t off = (uint32_t)(row * 64 +
                               ((ks ^ ((row >> 1) & 3)) << 4));
                ldsm4(Bh2[np], st + OFF_BH + off);
            }
            #pragma unroll
            for (int mi = 0; mi < 2; mi++)
                #pragma unroll
                for (int ni = 0; ni < 4; ni++)
                    mma_f16(acc[mi][ni], Ahr[mi], &Bh2[ni >> 1][(ni & 1) * 2]);
            #pragma unroll
            for (int mi = 0; mi < 2; mi++)
                #pragma unroll
                for (int ni = 0; ni < 4; ni++)
                    mma_f16(acc[mi][ni], Alr[mi], &Bh2[ni >> 1][(ni & 1) * 2]);
        }
        __syncthreads();
    }

    // ---- epilogue ----
    const int gr = lane >> 2, gc = (lane & 3) * 2;
    #pragma unroll
    for (int mi = 0; mi < 2; mi++) {
        #pragma unroll
        for (int h = 0; h < 2; h++) {
            int row = m0 + wr * 32 + mi * 16 + gr + h * 8;
            size_t roff = (size_t)row * ldC;
            #pragma unroll
            for (int ni = 0; ni < 4; ni++) {
                int col = n0 + wc * 32 + ni * 8 + gc;
                if (SPLITOUT) {
                    if (col >= Nstore) continue;
                } else {
                    if (col >= Nact) continue;
                }
                float v0 = acc[mi][ni][h * 2];
                float v1 = acc[mi][ni][h * 2 + 1];
                if (SPLITOUT && col >= Nact) { v0 = 0.f; v1 = 0.f; }
                else {
                    if (EPI == 1 || EPI == 2) { v0 += bias[col]; v1 += bias[col + 1]; }
                    if (EPI == 2) {
                        float u0 = 0.7978845608028654f * (v0 + 0.044715f * v0 * v0 * v0);
                        v0 = 0.5f * v0 * (1.0f + tanhf(u0));
                        float u1 = 0.7978845608028654f * (v1 + 0.044715f * v1 * v1 * v1);
                        v1 = 0.5f * v1 * (1.0f + tanhf(u1));
                    }
                    if (EPI == 3) {
                        v0 += res[roff + col];
                        v1 += res[roff + col + 1];
                    }
                }
                if (SPLITOUT) {
                    __half h0, l0, h1, l1;
                    split_h(v0, h0, l0);
                    split_h(v1, h1, l1);
                    *reinterpret_cast<uint32_t*>(Ch + roff + col) = pack_h(h0, h1);
                    *reinterpret_cast<uint32_t*>(Cl + roff + col) = pack_h(l0, l1);
                } else {
                    *reinterpret_cast<float2*>(C + roff + col) = make_float2(v0, v1);
                }
            }
        }
    }
}

// ---------------------------------------------------------------------------
// Attention: one warp per (bs, head); RMSNorm + RoPE + 16x16 softmax.
// Output written as hi/lo fp16 planes for the proj GEMM.
// ---------------------------------------------------------------------------
__global__ __launch_bounds__(128)
void attn_kernel(const float* __restrict__ q_gamma,
                 const float* __restrict__ k_gamma)
{
    __shared__ float qs[4][TT][33];
    __shared__ float ks[4][TT][33];
    __shared__ float vs[4][TT][32];
    __shared__ float ps[4][TT][17];

    int warp = threadIdx.x >> 5;
    int lane = threadIdx.x & 31;
    int gw = blockIdx.x * 4 + warp;
    int head = gw % HEADS;
    int bs   = gw / HEADS;
    int b_idx = bs / S_SP;
    int s     = bs % S_SP;

    float q[TT], k[TT], v[TT];
    #pragma unroll
    for (int t = 0; t < TT; t++) {
        size_t base = ((size_t)(bs * TT + t)) * (3 * CDIM) + head * HDIM + lane;
        q[t] = g_qkv[base];
        k[t] = g_qkv[base + CDIM];
        v[t] = g_qkv[base + 2 * CDIM];
    }

    float qg = q_gamma[lane], kg = k_gamma[lane];
    float freq = 0.0f;
    if (lane < 24) {
        int p = lane >> 1;
        freq = exp2f(-8.0f * (float)(2 * p) / 24.0f);
    }

    #pragma unroll
    for (int t = 0; t < TT; t++) {
        float sq = q[t] * q[t];
        float sk = k[t] * k[t];
        #pragma unroll
        for (int o = 16; o > 0; o >>= 1) {
            sq += __shfl_xor_sync(0xffffffffu, sq, o);
            sk += __shfl_xor_sync(0xffffffffu, sk, o);
        }
        float qn = q[t] * rsqrtf(sq * (1.0f / 32.0f) + 1e-6f) * qg;
        float kn = k[t] * rsqrtf(sk * (1.0f / 32.0f) + 1e-6f) * kg;

        float c = 1.0f, sn = 0.0f;
        if (lane < 24) {
            float ang = freq * (float)t;
            c = cosf(ang);
            sn = sinf(ang);
        }
        float qr = __shfl_xor_sync(0xffffffffu, qn, 1);
        float kr = __shfl_xor_sync(0xffffffffu, kn, 1);
        qr = (lane & 1) ? qr : -qr;
        kr = (lane & 1) ? kr : -kr;

        qs[warp][t][lane] = qn * c + qr * sn;
        ks[warp][t][lane] = kn * c + kr * sn;
        vs[warp][t][lane] = v[t];
    }
    __syncwarp();

    const float scale = 0.17677669529663687f;
    #pragma unroll
    for (int i = 0; i < 8; i++) {
        int idx = lane * 8 + i;
        int t = idx >> 4, m = idx & 15;
        float sum = 0.0f;
        #pragma unroll
        for (int d = 0; d < HDIM; d++)
            sum = fmaf(qs[warp][t][d], ks[warp][m][d], sum);
        ps[warp][t][m] = sum * scale;
    }
    __syncwarp();

    if (lane < 16) {
        float mx = -1e30f;
        #pragma unroll
        for (int m = 0; m < 16; m++) mx = fmaxf(mx, ps[warp][lane][m]);
        float sum = 0.0f;
        #pragma unroll
        for (int m = 0; m < 16; m++) {
            float e = expf(ps[warp][lane][m] - mx);
            ps[warp][lane][m] = e;
            sum += e;
        }
        float inv = 1.0f / sum;
        #pragma unroll
        for (int m = 0; m < 16; m++) ps[warp][lane][m] *= inv;
    }
    __syncwarp();

    #pragma unroll
    for (int t = 0; t < TT; t++) {
        float o = 0.0f;
        #pragma unroll
        for (int m = 0; m < 16; m++)
            o = fmaf(ps[warp][t][m], vs[warp][m][lane], o);
        size_t orow = (size_t)b_idx * (TT * S_SP) + (size_t)t * S_SP + s;
        __half h, l;
        split_h(o, h, l);
        g_ath[orow * CDIM + head * HDIM + lane] = h;
        g_atl[orow * CDIM + head * HDIM + lane] = l;
    }
}

// ---------------------------------------------------------------------------
extern "C" void kernel_launch(void* const* d_in, const int* in_sizes, int n_in,
                              void* d_out, int out_size)
{
    const float* mouse = (const float*)d_in[0];
    const float* x     = (const float*)d_in[2];
    const float* w1    = (const float*)d_in[3];
    const float* b1    = (const float*)d_in[4];
    const float* w2    = (const float*)d_in[5];
    const float* b2    = (const float*)d_in[6];
    const float* qkvw  = (const float*)d_in[7];
    const float* qg    = (const float*)d_in[8];
    const float* kg    = (const float*)d_in[9];
    const float* pw    = (const float*)d_in[10];
    float* out = (float*)d_out;

    cudaFuncSetAttribute(mma_gemm<2,1>, cudaFuncAttributeMaxDynamicSharedMemorySize, SMEM_SZ);
    cudaFuncSetAttribute(mma_gemm<1,1>, cudaFuncAttributeMaxDynamicSharedMemorySize, SMEM_SZ);
    cudaFuncSetAttribute(mma_gemm<0,0>, cudaFuncAttributeMaxDynamicSharedMemorySize, SMEM_SZ);
    cudaFuncSetAttribute(mma_gemm<3,0>, cudaFuncAttributeMaxDynamicSharedMemorySize, SMEM_SZ);

    __half *w1p, *w2p, *w3p, *w4p;
    cudaGetSymbolAddress((void**)&w1p, g_w1);
    cudaGetSymbolAddress((void**)&w2p, g_w2);
    cudaGetSymbolAddress((void**)&w3p, g_w3);
    cudaGetSymbolAddress((void**)&w4p, g_w4);

    __half *zh, *zl, *hh, *hl, *fh, *fl, *ath, *atl;
    cudaGetSymbolAddress((void**)&zh, g_zh);  cudaGetSymbolAddress((void**)&zl, g_zl);
    cudaGetSymbolAddress((void**)&hh, g_hh);  cudaGetSymbolAddress((void**)&hl, g_hl);
    cudaGetSymbolAddress((void**)&fh, g_fh);  cudaGetSymbolAddress((void**)&fl, g_fl);
    cudaGetSymbolAddress((void**)&ath, g_ath); cudaGetSymbolAddress((void**)&atl, g_atl);
    float* qkvP;
    cudaGetSymbolAddress((void**)&qkvP, g_qkv);

    dim3 cb(32, 8);
    conv_weight<<<dim3(1024/32, KP1/32), cb>>>(w1,   w1p, 792, 792,  KP1);
    conv_weight<<<dim3( 768/32, KP1/32), cb>>>(w2,   w2p, 792, 768,  KP1);
    conv_weight<<<dim3(2304/32, 768/32), cb>>>(qkvw, w3p, 768, 2304, 768);
    conv_weight<<<dim3( 768/32, 768/32), cb>>>(pw,   w4p, 768, 768,  768);

    build_z_kernel<<<NROWS, 128>>>(x, mouse);

    // h = gelu(z @ w1 + b1) -> split   N=792 (7 tiles), Nstore=832, K=832
    mma_gemm<2,1><<<dim3(7, NROWS/128), 512, SMEM_SZ>>>(
        zh, zl, w1p, b1, nullptr, nullptr, hh, hl, 792, KP1, KP1, KP1);
    // feat = h @ w2 + b2 -> split      N=768, K=832
    mma_gemm<1,1><<<dim3(6, NROWS/128), 512, SMEM_SZ>>>(
        hh, hl, w2p, b2, nullptr, nullptr, fh, fl, 768, 768, KP1, CDIM);
    // qkv = feat @ qkv_w -> fp32       N=2304, K=768
    mma_gemm<0,0><<<dim3(18, NROWS/128), 512, SMEM_SZ>>>(
        fh, fl, w3p, nullptr, nullptr, qkvP, nullptr, nullptr,
        2304, 2304, 768, 3*CDIM);

    attn_kernel<<<(BATCH * S_SP * HEADS) / 4, 128>>>(qg, kg);

    // out = x + attn @ proj_w -> fp32  N=768, K=768
    mma_gemm<3,0><<<dim3(6, NROWS/128), 512, SMEM_SZ>>>(
        ath, atl, w4p, nullptr, x, out, nullptr, nullptr,
        768, 768, 768, CDIM);

    (void)in_sizes; (void)n_in; (void)out_size;
}

// round 12
// speedup vs baseline: 4.9858x; 1.4268x over previous
#include <cuda_runtime.h>
#include <cuda_fp16.h>
#include <math.h>
#include <stdint.h>

// Problem constants (fixed by setup_inputs)
#define HEADS  24
#define HDIM   32
#define TT     16
#define S_SP   1560            // th*tw
#define BATCH  2
#define CDIM   768
#define INMLP  792
#define NROWS  (BATCH*S_SP*TT) // 49920
#define NF     61
#define PADT   12
#define KP1    832             // padded K for layer1/2 inputs

// ---------------------------------------------------------------------------
// Scratch (static device globals; no runtime allocation)
// Single fp16 plane everywhere (error ~u/sqrt(K) per GEMM, measured safe)
// ---------------------------------------------------------------------------
__device__ __half g_z [(size_t)NROWS * KP1];
__device__ __half g_h [(size_t)NROWS * KP1];
__device__ __half g_f [(size_t)NROWS * CDIM];
__device__ __half g_at[(size_t)NROWS * CDIM];
__device__ float g_qkv[(size_t)NROWS * 3 * CDIM];

// Pre-transposed fp16 weights: [Npad][Kpad], K contiguous
__device__ __half g_w1[(size_t)1024 * KP1];
__device__ __half g_w2[(size_t)768  * KP1];
__device__ __half g_w3[(size_t)2304 * 768];
__device__ __half g_w4[(size_t)768  * 768];

// ---------------------------------------------------------------------------
// helpers
// ---------------------------------------------------------------------------
__device__ __forceinline__ uint32_t s2u(const void* p) {
    uint32_t a;
    asm("{ .reg .u64 t; cvta.to.shared.u64 t, %1; cvt.u32.u64 %0, t; }"
        : "=r"(a) : "l"(p));
    return a;
}

__device__ __forceinline__ void ldsm4(uint32_t* r, uint32_t a) {
    asm volatile("ldmatrix.sync.aligned.m8n8.x4.shared.b16 {%0,%1,%2,%3}, [%4];"
        : "=r"(r[0]), "=r"(r[1]), "=r"(r[2]), "=r"(r[3]) : "r"(a));
}

__device__ __forceinline__ void mma_f16(float* d, const uint32_t* a,
                                        const uint32_t* b) {
    asm volatile(
        "mma.sync.aligned.m16n8k16.row.col.f32.f16.f16.f32 "
        "{%0,%1,%2,%3}, {%4,%5,%6,%7}, {%8,%9}, {%0,%1,%2,%3};"
        : "+f"(d[0]), "+f"(d[1]), "+f"(d[2]), "+f"(d[3])
        : "r"(a[0]), "r"(a[1]), "r"(a[2]), "r"(a[3]), "r"(b[0]), "r"(b[1]));
}

__device__ __forceinline__ void cp16(uint32_t dst, const void* src) {
    asm volatile("cp.async.cg.shared.global [%0], [%1], 16;"
                 :: "r"(dst), "l"(src) : "memory");
}

__device__ __forceinline__ uint32_t pack_h(__half a, __half b) {
    return ((uint32_t)__half_as_ushort(b) << 16) | __half_as_ushort(a);
}

__device__ __forceinline__ uint32_t pack_f2h(float a, float b) {
    uint32_t r;
    asm("cvt.rn.f16x2.f32 %0, %1, %2;" : "=r"(r) : "f"(b), "f"(a));
    return r;
}

// ---------------------------------------------------------------------------
// Weight transpose to fp16: W(K x N fp32) -> [Npad][Kpad] fp16
// ---------------------------------------------------------------------------
__global__ void conv_weight(const float* __restrict__ W,
                            __half* __restrict__ out,
                            int K, int N, int Kpad) {
    __shared__ float t[32][33];
    int n0 = blockIdx.x * 32, k0 = blockIdx.y * 32;
    int tx = threadIdx.x, ty = threadIdx.y;  // 32 x 8
    #pragma unroll
    for (int j = 0; j < 32; j += 8) {
        int k = k0 + ty + j, n = n0 + tx;
        t[ty + j][tx] = (k < K && n < N) ? W[(size_t)k * N + n] : 0.0f;
    }
    __syncthreads();
    #pragma unroll
    for (int j = 0; j < 32; j += 8) {
        int n = n0 + ty + j, k = k0 + tx;
        out[(size_t)n * Kpad + k] = __float2half_rn(t[tx][ty + j]);
    }
}

// ---------------------------------------------------------------------------
// build z (fp16) = concat(x_row, gathered mouse, zero pad to 832)
// ---------------------------------------------------------------------------
__global__ void build_z_kernel(const float* __restrict__ x,
                               const float* __restrict__ mouse) {
    int r = blockIdx.x;
    int bs = r / TT, t = r % TT;
    int b_idx = bs / S_SP, s = bs % S_SP;

    const float* xr = x + ((size_t)b_idx * (TT * S_SP) + (size_t)t * S_SP + s) * CDIM;
    __half* z = g_z + (size_t)r * KP1;

    for (int g = threadIdx.x; g < CDIM / 4; g += blockDim.x) {
        float4 v = reinterpret_cast<const float4*>(xr)[g];
        reinterpret_cast<uint2*>(z)[g] =
            make_uint2(pack_f2h(v.x, v.y), pack_f2h(v.z, v.w));
    }

    if (threadIdx.x < 64) {
        int col = CDIM + threadIdx.x;    // 768..831
        float v = 0.0f;
        if (col < INMLP) {
            int j  = (col - CDIM) >> 1;
            int ch = (col - CDIM) & 1;
            int i  = 4 * t + j;
            if (i >= PADT) v = mouse[((size_t)b_idx * NF + (i - PADT)) * 2 + ch];
        }
        z[col] = __float2half_rn(v);
    }
}

// ---------------------------------------------------------------------------
// fp16 single-pass GEMM on HMMA, cp.async 4-stage pipeline.
// CTA 128x128, 512 threads, 16 warps (4x4), warp tile 32x32, BK=32.
// EPI: 0 none, 1 +bias, 2 +bias+gelu, 3 +residual
// HALFOUT: 1 -> write fp16 plane, 0 -> fp32 C
// ---------------------------------------------------------------------------
#define OFF_A 0
#define OFF_B 8192
#define STAGE  16384
#define NSTAGE 4
#define SMEM_SZ (NSTAGE*STAGE)

template<int EPI, int HALFOUT>
__global__ void __launch_bounds__(512, 1)
mma_gemm(const __half* __restrict__ A_g,
         const __half* __restrict__ B_g,
         const float* __restrict__ bias,
         const float* __restrict__ res,
         float* __restrict__ C,
         __half* __restrict__ Ch,
         int Nact, int Nstore, int Kpad, int ldC)
{
    extern __shared__ char smem[];
    const uint32_t sb = s2u(smem);
    const int tid = threadIdx.x, wid = tid >> 5, lane = tid & 31;
    const int m0 = blockIdx.y * 128, n0 = blockIdx.x * 128;
    const int wr = wid & 3, wc = wid >> 2;      // 4x4 warp grid
    const int NCH = Kpad >> 5;

    // one 16B segment per thread per plane (512 segs per 8KB plane)
    const int r0 = tid >> 2, sg0 = tid & 3;
    const uint32_t off0 = (uint32_t)(r0 * 64 + ((sg0 ^ ((r0 >> 1) & 3)) << 4));
    const size_t ga0 = (size_t)(m0 + r0) * Kpad + sg0 * 8;
    const size_t gb0 = (size_t)(n0 + r0) * Kpad + sg0 * 8;

    auto issue = [&](int c) {
        if (c < NCH) {
            const uint32_t st = sb + (uint32_t)(c & (NSTAGE - 1)) * STAGE;
            const int k0 = c * 32;
            cp16(st + OFF_A + off0, A_g + ga0 + k0);
            cp16(st + OFF_B + off0, B_g + gb0 + k0);
        }
        asm volatile("cp.async.commit_group;" ::: "memory");
    };

    issue(0); issue(1); issue(2);

    float acc[2][4][4] = {};

    const int a_r = lane & 15;
    const int a_s = lane >> 4;
    const int b_n = (lane & 7) + ((lane >> 4) << 3);
    const int b_s = (lane >> 3) & 1;

    for (int c = 0; c < NCH; c++) {
        asm volatile("cp.async.wait_group %0;" :: "n"(NSTAGE - 2) : "memory");
        __syncthreads();
        issue(c + NSTAGE - 1);

        const uint32_t st = sb + (uint32_t)(c & (NSTAGE - 1)) * STAGE;
        #pragma unroll
        for (int step = 0; step < 2; step++) {
            uint32_t Ar[2][4], Br[2][4];
            #pragma unroll
            for (int mi = 0; mi < 2; mi++) {
                int row = wr * 32 + mi * 16 + a_r;
                int ks = step * 2 + a_s;
                uint32_t off = (uint32_t)(row * 64 +
                               ((ks ^ ((row >> 1) & 3)) << 4));
                ldsm4(Ar[mi], st + OFF_A + off);
            }
            #pragma unroll
            for (int np = 0; np < 2; np++) {
                int row = wc * 32 + np * 16 + b_n;
                int ks = step * 2 + b_s;
                uint32_t off = (uint32_t)(row * 64 +
                               ((ks ^ ((row >> 1) & 3)) << 4));
                ldsm4(Br[np], st + OFF_B + off);
            }
            #pragma unroll
            for (int mi = 0; mi < 2; mi++)
                #pragma unroll
                for (int ni = 0; ni < 4; ni++)
                    mma_f16(acc[mi][ni], Ar[mi], &Br[ni >> 1][(ni & 1) * 2]);
        }
        __syncthreads();
    }

    // ---- epilogue ----
    const int gr = lane >> 2, gc = (lane & 3) * 2;
    #pragma unroll
    for (int mi = 0; mi < 2; mi++) {
        #pragma unroll
        for (int h = 0; h < 2; h++) {
            int row = m0 + wr * 32 + mi * 16 + gr + h * 8;
            size_t roff = (size_t)row * ldC;
            #pragma unroll
            for (int ni = 0; ni < 4; ni++) {
                int col = n0 + wc * 32 + ni * 8 + gc;
                if (HALFOUT) {
                    if (col >= Nstore) continue;
                } else {
                    if (col >= Nact) continue;
                }
                float v0 = acc[mi][ni][h * 2];
                float v1 = acc[mi][ni][h * 2 + 1];
                if (HALFOUT && col >= Nact) { v0 = 0.f; v1 = 0.f; }
                else {
                    if (EPI == 1 || EPI == 2) { v0 += bias[col]; v1 += bias[col + 1]; }
                    if (EPI == 2) {
                        float u0 = 0.7978845608028654f * (v0 + 0.044715f * v0 * v0 * v0);
                        v0 = 0.5f * v0 * (1.0f + tanhf(u0));
                        float u1 = 0.7978845608028654f * (v1 + 0.044715f * v1 * v1 * v1);
                        v1 = 0.5f * v1 * (1.0f + tanhf(u1));
                    }
                    if (EPI == 3) {
                        v0 += res[roff + col];
                        v1 += res[roff + col + 1];
                    }
                }
                if (HALFOUT) {
                    *reinterpret_cast<uint32_t*>(Ch + roff + col) = pack_f2h(v0, v1);
                } else {
                    *reinterpret_cast<float2*>(C + roff + col) = make_float2(v0, v1);
                }
            }
        }
    }
}

// ---------------------------------------------------------------------------
// Attention: one warp per (bs, head); RMSNorm + RoPE + 16x16 softmax.
// Output written as fp16 for the proj GEMM.
// ---------------------------------------------------------------------------
__global__ __launch_bounds__(128)
void attn_kernel(const float* __restrict__ q_gamma,
                 const float* __restrict__ k_gamma)
{
    __shared__ float qs[4][TT][33];
    __shared__ float ks[4][TT][33];
    __shared__ float vs[4][TT][32];
    __shared__ float ps[4][TT][17];

    int warp = threadIdx.x >> 5;
    int lane = threadIdx.x & 31;
    int gw = blockIdx.x * 4 + warp;
    int head = gw % HEADS;
    int bs   = gw / HEADS;
    int b_idx = bs / S_SP;
    int s     = bs % S_SP;

    float q[TT], k[TT], v[TT];
    #pragma unroll
    for (int t = 0; t < TT; t++) {
        size_t base = ((size_t)(bs * TT + t)) * (3 * CDIM) + head * HDIM + lane;
        q[t] = g_qkv[base];
        k[t] = g_qkv[base + CDIM];
        v[t] = g_qkv[base + 2 * CDIM];
    }

    float qg = q_gamma[lane], kg = k_gamma[lane];
    float freq = 0.0f;
    if (lane < 24) {
        int p = lane >> 1;
        freq = exp2f(-8.0f * (float)(2 * p) / 24.0f);
    }

    #pragma unroll
    for (int t = 0; t < TT; t++) {
        float sq = q[t] * q[t];
        float sk = k[t] * k[t];
        #pragma unroll
        for (int o = 16; o > 0; o >>= 1) {
            sq += __shfl_xor_sync(0xffffffffu, sq, o);
            sk += __shfl_xor_sync(0xffffffffu, sk, o);
        }
        float qn = q[t] * rsqrtf(sq * (1.0f / 32.0f) + 1e-6f) * qg;
        float kn = k[t] * rsqrtf(sk * (1.0f / 32.0f) + 1e-6f) * kg;

        float c = 1.0f, sn = 0.0f;
        if (lane < 24) {
            float ang = freq * (float)t;
            c = cosf(ang);
            sn = sinf(ang);
        }
        float qr = __shfl_xor_sync(0xffffffffu, qn, 1);
        float kr = __shfl_xor_sync(0xffffffffu, kn, 1);
        qr = (lane & 1) ? qr : -qr;
        kr = (lane & 1) ? kr : -kr;

        qs[warp][t][lane] = qn * c + qr * sn;
        ks[warp][t][lane] = kn * c + kr * sn;
        vs[warp][t][lane] = v[t];
    }
    __syncwarp();

    const float scale = 0.17677669529663687f;
    #pragma unroll
    for (int i = 0; i < 8; i++) {
        int idx = lane * 8 + i;
        int t = idx >> 4, m = idx & 15;
        float sum = 0.0f;
        #pragma unroll
        for (int d = 0; d < HDIM; d++)
            sum = fmaf(qs[warp][t][d], ks[warp][m][d], sum);
        ps[warp][t][m] = sum * scale;
    }
    __syncwarp();

    if (lane < 16) {
        float mx = -1e30f;
        #pragma unroll
        for (int m = 0; m < 16; m++) mx = fmaxf(mx, ps[warp][lane][m]);
        float sum = 0.0f;
        #pragma unroll
        for (int m = 0; m < 16; m++) {
            float e = expf(ps[warp][lane][m] - mx);
            ps[warp][lane][m] = e;
            sum += e;
        }
        float inv = 1.0f / sum;
        #pragma unroll
        for (int m = 0; m < 16; m++) ps[warp][lane][m] *= inv;
    }
    __syncwarp();

    #pragma unroll
    for (int t = 0; t < TT; t++) {
        float o = 0.0f;
        #pragma unroll
        for (int m = 0; m < 16; m++)
            o = fmaf(ps[warp][t][m], vs[warp][m][lane], o);
        size_t orow = (size_t)b_idx * (TT * S_SP) + (size_t)t * S_SP + s;
        g_at[orow * CDIM + head * HDIM + lane] = __float2half_rn(o);
    }
}

// ---------------------------------------------------------------------------
extern "C" void kernel_launch(void* const* d_in, const int* in_sizes, int n_in,
                              void* d_out, int out_size)
{
    const float* mouse = (const float*)d_in[0];
    const float* x     = (const float*)d_in[2];
    const float* w1    = (const float*)d_in[3];
    const float* b1    = (const float*)d_in[4];
    const float* w2    = (const float*)d_in[5];
    const float* b2    = (const float*)d_in[6];
    const float* qkvw  = (const float*)d_in[7];
    const float* qg    = (const float*)d_in[8];
    const float* kg    = (const float*)d_in[9];
    const float* pw    = (const float*)d_in[10];
    float* out = (float*)d_out;

    cudaFuncSetAttribute(mma_gemm<2,1>, cudaFuncAttributeMaxDynamicSharedMemorySize, SMEM_SZ);
    cudaFuncSetAttribute(mma_gemm<1,1>, cudaFuncAttributeMaxDynamicSharedMemorySize, SMEM_SZ);
    cudaFuncSetAttribute(mma_gemm<0,0>, cudaFuncAttributeMaxDynamicSharedMemorySize, SMEM_SZ);
    cudaFuncSetAttribute(mma_gemm<3,0>, cudaFuncAttributeMaxDynamicSharedMemorySize, SMEM_SZ);

    __half *w1p, *w2p, *w3p, *w4p;
    cudaGetSymbolAddress((void**)&w1p, g_w1);
    cudaGetSymbolAddress((void**)&w2p, g_w2);
    cudaGetSymbolAddress((void**)&w3p, g_w3);
    cudaGetSymbolAddress((void**)&w4p, g_w4);

    __half *zp, *hp, *fp, *atp;
    cudaGetSymbolAddress((void**)&zp, g_z);
    cudaGetSymbolAddress((void**)&hp, g_h);
    cudaGetSymbolAddress((void**)&fp, g_f);
    cudaGetSymbolAddress((void**)&atp, g_at);
    float* qkvP;
    cudaGetSymbolAddress((void**)&qkvP, g_qkv);

    dim3 cb(32, 8);
    conv_weight<<<dim3(1024/32, KP1/32), cb>>>(w1,   w1p, 792, 792,  KP1);
    conv_weight<<<dim3( 768/32, KP1/32), cb>>>(w2,   w2p, 792, 768,  KP1);
    conv_weight<<<dim3(2304/32, 768/32), cb>>>(qkvw, w3p, 768, 2304, 768);
    conv_weight<<<dim3( 768/32, 768/32), cb>>>(pw,   w4p, 768, 768,  768);

    build_z_kernel<<<NROWS, 128>>>(x, mouse);

    // h = gelu(z @ w1 + b1) -> fp16    N=792 (7 tiles), Nstore=832, K=832
    mma_gemm<2,1><<<dim3(7, NROWS/128), 512, SMEM_SZ>>>(
        zp, w1p, b1, nullptr, nullptr, hp, 792, KP1, KP1, KP1);
    // feat = h @ w2 + b2 -> fp16       N=768, K=832
    mma_gemm<1,1><<<dim3(6, NROWS/128), 512, SMEM_SZ>>>(
        hp, w2p, b2, nullptr, nullptr, fp, 768, 768, KP1, CDIM);
    // qkv = feat @ qkv_w -> fp32       N=2304, K=768
    mma_gemm<0,0><<<dim3(18, NROWS/128), 512, SMEM_SZ>>>(
        fp, w3p, nullptr, nullptr, qkvP, nullptr, 2304, 2304, 768, 3*CDIM);

    attn_kernel<<<(BATCH * S_SP * HEADS) / 4, 128>>>(qg, kg);

    // out = x + attn @ proj_w -> fp32  N=768, K=768
    mma_gemm<3,0><<<dim3(6, NROWS/128), 512, SMEM_SZ>>>(
        atp, w4p, nullptr, x, out, nullptr, 768, 768, 768, CDIM);

    (void)in_sizes; (void)n_in; (void)out_size;
}

// round 13
// speedup vs baseline: 6.5630x; 1.3163x over previous
#include <cuda_runtime.h>
#include <cuda_fp16.h>
#include <math.h>
#include <stdint.h>

// Problem constants (fixed by setup_inputs)
#define HEADS  24
#define HDIM   32
#define TT     16
#define S_SP   1560            // th*tw
#define BATCH  2
#define CDIM   768
#define INMLP  792
#define NROWS  (BATCH*S_SP*TT) // 49920
#define NF     61
#define PADT   12
#define KP1    832             // padded K for layer1/2 inputs

// ---------------------------------------------------------------------------
// Scratch (static device globals; no runtime allocation) — all fp16 planes
// ---------------------------------------------------------------------------
__device__ __half g_z [(size_t)NROWS * KP1];
__device__ __half g_h [(size_t)NROWS * KP1];
__device__ __half g_f [(size_t)NROWS * CDIM];
__device__ __half g_at[(size_t)NROWS * CDIM];
__device__ __half g_qkv[(size_t)NROWS * 3 * CDIM];

// Pre-transposed fp16 weights: [Npad][Kpad], K contiguous
__device__ __half g_w1[(size_t)1024 * KP1];
__device__ __half g_w2[(size_t)768  * KP1];
__device__ __half g_w3[(size_t)2304 * 768];
__device__ __half g_w4[(size_t)768  * 768];

// ---------------------------------------------------------------------------
// helpers
// ---------------------------------------------------------------------------
__device__ __forceinline__ uint32_t s2u(const void* p) {
    uint32_t a;
    asm("{ .reg .u64 t; cvta.to.shared.u64 t, %1; cvt.u32.u64 %0, t; }"
        : "=r"(a) : "l"(p));
    return a;
}

__device__ __forceinline__ void ldsm4(uint32_t* r, uint32_t a) {
    asm volatile("ldmatrix.sync.aligned.m8n8.x4.shared.b16 {%0,%1,%2,%3}, [%4];"
        : "=r"(r[0]), "=r"(r[1]), "=r"(r[2]), "=r"(r[3]) : "r"(a));
}

__device__ __forceinline__ void mma_f16(float* d, const uint32_t* a,
                                        const uint32_t* b) {
    asm volatile(
        "mma.sync.aligned.m16n8k16.row.col.f32.f16.f16.f32 "
        "{%0,%1,%2,%3}, {%4,%5,%6,%7}, {%8,%9}, {%0,%1,%2,%3};"
        : "+f"(d[0]), "+f"(d[1]), "+f"(d[2]), "+f"(d[3])
        : "r"(a[0]), "r"(a[1]), "r"(a[2]), "r"(a[3]), "r"(b[0]), "r"(b[1]));
}

__device__ __forceinline__ void cp16(uint32_t dst, const void* src) {
    asm volatile("cp.async.cg.shared.global [%0], [%1], 16;"
                 :: "r"(dst), "l"(src) : "memory");
}

__device__ __forceinline__ uint32_t pack_f2h(float a, float b) {
    uint32_t r;
    asm("cvt.rn.f16x2.f32 %0, %1, %2;" : "=r"(r) : "f"(b), "f"(a));
    return r;
}

// ---------------------------------------------------------------------------
// Weight transpose to fp16: W(K x N fp32) -> [Npad][Kpad] fp16
// ---------------------------------------------------------------------------
__global__ void conv_weight(const float* __restrict__ W,
                            __half* __restrict__ out,
                            int K, int N, int Kpad) {
    __shared__ float t[32][33];
    int n0 = blockIdx.x * 32, k0 = blockIdx.y * 32;
    int tx = threadIdx.x, ty = threadIdx.y;  // 32 x 8
    #pragma unroll
    for (int j = 0; j < 32; j += 8) {
        int k = k0 + ty + j, n = n0 + tx;
        t[ty + j][tx] = (k < K && n < N) ? W[(size_t)k * N + n] : 0.0f;
    }
    __syncthreads();
    #pragma unroll
    for (int j = 0; j < 32; j += 8) {
        int n = n0 + ty + j, k = k0 + tx;
        out[(size_t)n * Kpad + k] = __float2half_rn(t[tx][ty + j]);
    }
}

// ---------------------------------------------------------------------------
// build z (fp16) = concat(x_row, gathered mouse, zero pad to 832)
// ---------------------------------------------------------------------------
__global__ void build_z_kernel(const float* __restrict__ x,
                               const float* __restrict__ mouse) {
    int r = blockIdx.x;
    int bs = r / TT, t = r % TT;
    int b_idx = bs / S_SP, s = bs % S_SP;

    const float* xr = x + ((size_t)b_idx * (TT * S_SP) + (size_t)t * S_SP + s) * CDIM;
    __half* z = g_z + (size_t)r * KP1;

    for (int g = threadIdx.x; g < CDIM / 4; g += blockDim.x) {
        float4 v = reinterpret_cast<const float4*>(xr)[g];
        reinterpret_cast<uint2*>(z)[g] =
            make_uint2(pack_f2h(v.x, v.y), pack_f2h(v.z, v.w));
    }

    if (threadIdx.x < 64) {
        int col = CDIM + threadIdx.x;    // 768..831
        float v = 0.0f;
        if (col < INMLP) {
            int j  = (col - CDIM) >> 1;
            int ch = (col - CDIM) & 1;
            int i  = 4 * t + j;
            if (i >= PADT) v = mouse[((size_t)b_idx * NF + (i - PADT)) * 2 + ch];
        }
        z[col] = __float2half_rn(v);
    }
}

// ---------------------------------------------------------------------------
// fp16 single-pass GEMM on HMMA; BK=64, 3-stage cp.async pipeline.
// CTA 128x128, 256 threads, 8 warps (2x4), warp tile 64x32.
// EPI: 0 none, 1 +bias, 2 +bias+gelu, 3 +residual
// HALFOUT: 1 -> write fp16 plane, 0 -> fp32 C
// ---------------------------------------------------------------------------
#define OFF_A 0
#define OFF_B 16384
#define STAGE  32768          // A 16K + B 16K (128 rows x 128 bytes each)
#define NSTAGE 3
#define SMEM_SZ (NSTAGE*STAGE)

template<int EPI, int HALFOUT>
__global__ void __launch_bounds__(256, 2)
mma_gemm(const __half* __restrict__ A_g,
         const __half* __restrict__ B_g,
         const float* __restrict__ bias,
         const float* __restrict__ res,
         float* __restrict__ C,
         __half* __restrict__ Ch,
         int Nact, int Nstore, int Kpad, int ldC)
{
    extern __shared__ char smem[];
    const uint32_t sb = s2u(smem);
    const int tid = threadIdx.x, wid = tid >> 5, lane = tid & 31;
    const int m0 = blockIdx.y * 128, n0 = blockIdx.x * 128;
    const int wr = wid & 1, wc = wid >> 1;      // 2x4 warp grid
    const int NCH = Kpad >> 6;

    // loads: 1024 16B-segments per plane; 4 per thread per plane.
    // e = i*256 + tid: row = i*32 + (tid>>3), sg = tid&7 (const),
    // swz = sg ^ ((tid>>3)&7) (const across i)
    const int sg0  = tid & 7;
    const int rb   = tid >> 3;               // 0..31
    const uint32_t swz16 = (uint32_t)((sg0 ^ (rb & 7)) << 4);

    auto issue = [&](int c) {
        if (c < NCH) {
            const uint32_t st = sb + (uint32_t)(c % NSTAGE) * STAGE;
            const int k0 = c * 64;
            #pragma unroll
            for (int i = 0; i < 4; i++) {
                int row = i * 32 + rb;
                uint32_t off = (uint32_t)(row * 128) + swz16;
                const __half* pa = A_g + (size_t)(m0 + row) * Kpad + k0 + sg0 * 8;
                const __half* pb = B_g + (size_t)(n0 + row) * Kpad + k0 + sg0 * 8;
                cp16(st + OFF_A + off, pa);
                cp16(st + OFF_B + off, pb);
            }
        }
        asm volatile("cp.async.commit_group;" ::: "memory");
    };

    issue(0); issue(1);

    float acc[4][4][4] = {};

    const int a_r = lane & 15;
    const int a_s = lane >> 4;
    const int b_n = (lane & 7) + ((lane >> 4) << 3);
    const int b_s = (lane >> 3) & 1;

    for (int c = 0; c < NCH; c++) {
        asm volatile("cp.async.wait_group %0;" :: "n"(1) : "memory");
        __syncthreads();
        issue(c + 2);

        const uint32_t st = sb + (uint32_t)(c % NSTAGE) * STAGE;
        #pragma unroll
        for (int step = 0; step < 4; step++) {
            uint32_t Ar[4][4], Br[2][4];
            #pragma unroll
            for (int mi = 0; mi < 4; mi++) {
                int row = wr * 64 + mi * 16 + a_r;
                int ks = step * 2 + a_s;
                uint32_t off = (uint32_t)(row * 128 +
                               ((ks ^ (row & 7)) << 4));
                ldsm4(Ar[mi], st + OFF_A + off);
            }
            #pragma unroll
            for (int np = 0; np < 2; np++) {
                int row = wc * 32 + np * 16 + b_n;
                int ks = step * 2 + b_s;
                uint32_t off = (uint32_t)(row * 128 +
                               ((ks ^ (row & 7)) << 4));
                ldsm4(Br[np], st + OFF_B + off);
            }
            #pragma unroll
            for (int mi = 0; mi < 4; mi++)
                #pragma unroll
                for (int ni = 0; ni < 4; ni++)
                    mma_f16(acc[mi][ni], Ar[mi], &Br[ni >> 1][(ni & 1) * 2]);
        }
        __syncthreads();
    }

    // ---- epilogue ----
    const int gr = lane >> 2, gc = (lane & 3) * 2;
    #pragma unroll
    for (int mi = 0; mi < 4; mi++) {
        #pragma unroll
        for (int h = 0; h < 2; h++) {
            int row = m0 + wr * 64 + mi * 16 + gr + h * 8;
            size_t roff = (size_t)row * ldC;
            #pragma unroll
            for (int ni = 0; ni < 4; ni++) {
                int col = n0 + wc * 32 + ni * 8 + gc;
                if (HALFOUT) {
                    if (col >= Nstore) continue;
                } else {
                    if (col >= Nact) continue;
                }
                float v0 = acc[mi][ni][h * 2];
                float v1 = acc[mi][ni][h * 2 + 1];
                if (HALFOUT && col >= Nact) { v0 = 0.f; v1 = 0.f; }
                else {
                    if (EPI == 1 || EPI == 2) { v0 += bias[col]; v1 += bias[col + 1]; }
                    if (EPI == 2) {
                        float u0 = 0.7978845608028654f * (v0 + 0.044715f * v0 * v0 * v0);
                        v0 = 0.5f * v0 * (1.0f + tanhf(u0));
                        float u1 = 0.7978845608028654f * (v1 + 0.044715f * v1 * v1 * v1);
                        v1 = 0.5f * v1 * (1.0f + tanhf(u1));
                    }
                    if (EPI == 3) {
                        v0 += res[roff + col];
                        v1 += res[roff + col + 1];
                    }
                }
                if (HALFOUT) {
                    *reinterpret_cast<uint32_t*>(Ch + roff + col) = pack_f2h(v0, v1);
                } else {
                    *reinterpret_cast<float2*>(C + roff + col) = make_float2(v0, v1);
                }
            }
        }
    }
}

// ---------------------------------------------------------------------------
// Attention: one warp per (bs, head); RMSNorm + RoPE + 16x16 softmax.
// qkv in fp16; output written fp16 for the proj GEMM.
// ---------------------------------------------------------------------------
__global__ __launch_bounds__(128)
void attn_kernel(const float* __restrict__ q_gamma,
                 const float* __restrict__ k_gamma)
{
    __shared__ float qs[4][TT][33];
    __shared__ float ks[4][TT][33];
    __shared__ float vs[4][TT][32];
    __shared__ float ps[4][TT][17];

    int warp = threadIdx.x >> 5;
    int lane = threadIdx.x & 31;
    int gw = blockIdx.x * 4 + warp;
    int head = gw % HEADS;
    int bs   = gw / HEADS;
    int b_idx = bs / S_SP;
    int s     = bs % S_SP;

    float q[TT], k[TT], v[TT];
    #pragma unroll
    for (int t = 0; t < TT; t++) {
        size_t base = ((size_t)(bs * TT + t)) * (3 * CDIM) + head * HDIM + lane;
        q[t] = __half2float(g_qkv[base]);
        k[t] = __half2float(g_qkv[base + CDIM]);
        v[t] = __half2float(g_qkv[base + 2 * CDIM]);
    }

    float qg = q_gamma[lane], kg = k_gamma[lane];
    float freq = 0.0f;
    if (lane < 24) {
        int p = lane >> 1;
        freq = exp2f(-8.0f * (float)(2 * p) / 24.0f);
    }

    #pragma unroll
    for (int t = 0; t < TT; t++) {
        float sq = q[t] * q[t];
        float sk = k[t] * k[t];
        #pragma unroll
        for (int o = 16; o > 0; o >>= 1) {
            sq += __shfl_xor_sync(0xffffffffu, sq, o);
            sk += __shfl_xor_sync(0xffffffffu, sk, o);
        }
        float qn = q[t] * rsqrtf(sq * (1.0f / 32.0f) + 1e-6f) * qg;
        float kn = k[t] * rsqrtf(sk * (1.0f / 32.0f) + 1e-6f) * kg;

        float c = 1.0f, sn = 0.0f;
        if (lane < 24) {
            float ang = freq * (float)t;
            c = cosf(ang);
            sn = sinf(ang);
        }
        float qr = __shfl_xor_sync(0xffffffffu, qn, 1);
        float kr = __shfl_xor_sync(0xffffffffu, kn, 1);
        qr = (lane & 1) ? qr : -qr;
        kr = (lane & 1) ? kr : -kr;

        qs[warp][t][lane] = qn * c + qr * sn;
        ks[warp][t][lane] = kn * c + kr * sn;
        vs[warp][t][lane] = v[t];
    }
    __syncwarp();

    const float scale = 0.17677669529663687f;
    #pragma unroll
    for (int i = 0; i < 8; i++) {
        int idx = lane * 8 + i;
        int t = idx >> 4, m = idx & 15;
        float sum = 0.0f;
        #pragma unroll
        for (int d = 0; d < HDIM; d++)
            sum = fmaf(qs[warp][t][d], ks[warp][m][d], sum);
        ps[warp][t][m] = sum * scale;
    }
    __syncwarp();

    if (lane < 16) {
        float mx = -1e30f;
        #pragma unroll
        for (int m = 0; m < 16; m++) mx = fmaxf(mx, ps[warp][lane][m]);
        float sum = 0.0f;
        #pragma unroll
        for (int m = 0; m < 16; m++) {
            float e = expf(ps[warp][lane][m] - mx);
            ps[warp][lane][m] = e;
            sum += e;
        }
        float inv = 1.0f / sum;
        #pragma unroll
        for (int m = 0; m < 16; m++) ps[warp][lane][m] *= inv;
    }
    __syncwarp();

    #pragma unroll
    for (int t = 0; t < TT; t++) {
        float o = 0.0f;
        #pragma unroll
        for (int m = 0; m < 16; m++)
            o = fmaf(ps[warp][t][m], vs[warp][m][lane], o);
        size_t orow = (size_t)b_idx * (TT * S_SP) + (size_t)t * S_SP + s;
        g_at[orow * CDIM + head * HDIM + lane] = __float2half_rn(o);
    }
}

// ---------------------------------------------------------------------------
extern "C" void kernel_launch(void* const* d_in, const int* in_sizes, int n_in,
                              void* d_out, int out_size)
{
    const float* mouse = (const float*)d_in[0];
    const float* x     = (const float*)d_in[2];
    const float* w1    = (const float*)d_in[3];
    const float* b1    = (const float*)d_in[4];
    const float* w2    = (const float*)d_in[5];
    const float* b2    = (const float*)d_in[6];
    const float* qkvw  = (const float*)d_in[7];
    const float* qg    = (const float*)d_in[8];
    const float* kg    = (const float*)d_in[9];
    const float* pw    = (const float*)d_in[10];
    float* out = (float*)d_out;

    cudaFuncSetAttribute(mma_gemm<2,1>, cudaFuncAttributeMaxDynamicSharedMemorySize, SMEM_SZ);
    cudaFuncSetAttribute(mma_gemm<1,1>, cudaFuncAttributeMaxDynamicSharedMemorySize, SMEM_SZ);
    cudaFuncSetAttribute(mma_gemm<0,1>, cudaFuncAttributeMaxDynamicSharedMemorySize, SMEM_SZ);
    cudaFuncSetAttribute(mma_gemm<3,0>, cudaFuncAttributeMaxDynamicSharedMemorySize, SMEM_SZ);

    __half *w1p, *w2p, *w3p, *w4p;
    cudaGetSymbolAddress((void**)&w1p, g_w1);
    cudaGetSymbolAddress((void**)&w2p, g_w2);
    cudaGetSymbolAddress((void**)&w3p, g_w3);
    cudaGetSymbolAddress((void**)&w4p, g_w4);

    __half *zp, *hp, *fp, *atp, *qkvP;
    cudaGetSymbolAddress((void**)&zp, g_z);
    cudaGetSymbolAddress((void**)&hp, g_h);
    cudaGetSymbolAddress((void**)&fp, g_f);
    cudaGetSymbolAddress((void**)&atp, g_at);
    cudaGetSymbolAddress((void**)&qkvP, g_qkv);

    dim3 cb(32, 8);
    conv_weight<<<dim3(1024/32, KP1/32), cb>>>(w1,   w1p, 792, 792,  KP1);
    conv_weight<<<dim3( 768/32, KP1/32), cb>>>(w2,   w2p, 792, 768,  KP1);
    conv_weight<<<dim3(2304/32, 768/32), cb>>>(qkvw, w3p, 768, 2304, 768);
    conv_weight<<<dim3( 768/32, 768/32), cb>>>(pw,   w4p, 768, 768,  768);

    build_z_kernel<<<NROWS, 128>>>(x, mouse);

    // h = gelu(z @ w1 + b1) -> fp16    N=792 (7 tiles), Nstore=832, K=832
    mma_gemm<2,1><<<dim3(7, NROWS/128), 256, SMEM_SZ>>>(
        zp, w1p, b1, nullptr, nullptr, hp, 792, KP1, KP1, KP1);
    // feat = h @ w2 + b2 -> fp16       N=768, K=832
    mma_gemm<1,1><<<dim3(6, NROWS/128), 256, SMEM_SZ>>>(
        hp, w2p, b2, nullptr, nullptr, fp, 768, 768, KP1, CDIM);
    // qkv = feat @ qkv_w -> fp16       N=2304, K=768
    mma_gemm<0,1><<<dim3(18, NROWS/128), 256, SMEM_SZ>>>(
        fp, w3p, nullptr, nullptr, nullptr, qkvP, 2304, 2304, 768, 3*CDIM);

    attn_kernel<<<(BATCH * S_SP * HEADS) / 4, 128>>>(qg, kg);

    // out = x + attn @ proj_w -> fp32  N=768, K=768
    mma_gemm<3,0><<<dim3(6, NROWS/128), 256, SMEM_SZ>>>(
        atp, w4p, nullptr, x, out, nullptr, 768, 768, 768, CDIM);

    (void)in_sizes; (void)n_in; (void)out_size;
}

// round 17
// speedup vs baseline: 7.1436x; 1.0885x over previous
#include <cuda_runtime.h>
#include <cuda_fp16.h>
#include <math.h>
#include <stdint.h>

// Problem constants (fixed by setup_inputs)
#define HEADS  24
#define HDIM   32
#define TT     16
#define S_SP   1560            // th*tw
#define BATCH  2
#define CDIM   768
#define INMLP  792
#define NROWS  (BATCH*S_SP*TT) // 49920
#define NF     61
#define PADT   12
#define KP1    832             // padded width of h (GEMM2 K)

// ---------------------------------------------------------------------------
// Scratch (static device globals; no runtime allocation) — all fp16 planes
// ---------------------------------------------------------------------------
__device__ __half g_x16[(size_t)NROWS * CDIM];     // fp16 copy of x
__device__ __half g_h [(size_t)NROWS * KP1];
__device__ __half g_f [(size_t)NROWS * CDIM];
__device__ __half g_at[(size_t)NROWS * CDIM];
__device__ __half g_qkv[(size_t)NROWS * 3 * CDIM];
__device__ float  g_bias2[32 * 800];               // per-(b,t) GEMM1 bias

// Pre-transposed fp16 weights: [Npad][Kpad], K contiguous
__device__ __half g_w1[(size_t)1024 * CDIM];       // K=768 now
__device__ __half g_w2[(size_t)768  * KP1];
__device__ __half g_w3[(size_t)2304 * 768];
__device__ __half g_w4[(size_t)768  * 768];

// ---------------------------------------------------------------------------
// helpers
// ---------------------------------------------------------------------------
__device__ __forceinline__ uint32_t s2u(const void* p) {
    uint32_t a;
    asm("{ .reg .u64 t; cvta.to.shared.u64 t, %1; cvt.u32.u64 %0, t; }"
        : "=r"(a) : "l"(p));
    return a;
}

__device__ __forceinline__ void ldsm4(uint32_t* r, uint32_t a) {
    asm volatile("ldmatrix.sync.aligned.m8n8.x4.shared.b16 {%0,%1,%2,%3}, [%4];"
        : "=r"(r[0]), "=r"(r[1]), "=r"(r[2]), "=r"(r[3]) : "r"(a));
}

__device__ __forceinline__ void mma_f16(float* d, const uint32_t* a,
                                        const uint32_t* b) {
    asm volatile(
        "mma.sync.aligned.m16n8k16.row.col.f32.f16.f16.f32 "
        "{%0,%1,%2,%3}, {%4,%5,%6,%7}, {%8,%9}, {%0,%1,%2,%3};"
        : "+f"(d[0]), "+f"(d[1]), "+f"(d[2]), "+f"(d[3])
        : "r"(a[0]), "r"(a[1]), "r"(a[2]), "r"(a[3]), "r"(b[0]), "r"(b[1]));
}

__device__ __forceinline__ void cp16(uint32_t dst, const void* src) {
    asm volatile("cp.async.cg.shared.global [%0], [%1], 16;"
                 :: "r"(dst), "l"(src) : "memory");
}

__device__ __forceinline__ uint32_t pack_f2h(float a, float b) {
    uint32_t r;
    asm("cvt.rn.f16x2.f32 %0, %1, %2;" : "=r"(r) : "f"(b), "f"(a));
    return r;
}

__device__ __forceinline__ float gelu_f(float v) {
    float u = 0.7978845608028654f * (v + 0.044715f * v * v * v);
    float t;
    asm("tanh.approx.f32 %0, %1;" : "=f"(t) : "f"(u));
    return 0.5f * v * (1.0f + t);
}

// ---------------------------------------------------------------------------
// Weight transpose to fp16: W(K x N fp32) -> [Npad][Kpad] fp16
// ---------------------------------------------------------------------------
__global__ void conv_weight(const float* __restrict__ W,
                            __half* __restrict__ out,
                            int K, int N, int Kpad) {
    __shared__ float t[32][33];
    int n0 = blockIdx.x * 32, k0 = blockIdx.y * 32;
    int tx = threadIdx.x, ty = threadIdx.y;  // 32 x 8
    #pragma unroll
    for (int j = 0; j < 32; j += 8) {
        int k = k0 + ty + j, n = n0 + tx;
        t[ty + j][tx] = (k < K && n < N) ? W[(size_t)k * N + n] : 0.0f;
    }
    __syncthreads();
    #pragma unroll
    for (int j = 0; j < 32; j += 8) {
        int n = n0 + ty + j, k = k0 + tx;
        out[(size_t)n * Kpad + k] = __float2half_rn(t[tx][ty + j]);
    }
}

// ---------------------------------------------------------------------------
// convert x (fp32) -> g_x16 (fp16), straight streaming copy
// ---------------------------------------------------------------------------
__global__ void convert_x(const float* __restrict__ x) {
    const float4* xin = reinterpret_cast<const float4*>(x);
    size_t n4 = (size_t)NROWS * CDIM / 4;
    for (size_t i = (size_t)blockIdx.x * blockDim.x + threadIdx.x; i < n4;
         i += (size_t)gridDim.x * blockDim.x) {
        float4 v = xin[i];
        reinterpret_cast<uint2*>(g_x16)[i] =
            make_uint2(pack_f2h(v.x, v.y), pack_f2h(v.z, v.w));
    }
}

// ---------------------------------------------------------------------------
// bias2[b*16+t][n] = b1[n] + sum_j gm[b,t,j] * w1[768+j][n]   (fp32)
// ---------------------------------------------------------------------------
__global__ void build_bias2(const float* __restrict__ mouse,
                            const float* __restrict__ w1,
                            const float* __restrict__ b1) {
    int bt = blockIdx.x, b = bt >> 4, t = bt & 15;
    float gm[24];
    #pragma unroll
    for (int j = 0; j < 24; j++) {
        int jj = j >> 1, ch = j & 1;
        int i = 4 * t + jj;
        gm[j] = (i >= PADT) ? mouse[((size_t)b * NF + (i - PADT)) * 2 + ch] : 0.0f;
    }
    for (int n = threadIdx.x; n < INMLP; n += blockDim.x) {
        float acc = b1[n];
        #pragma unroll
        for (int j = 0; j < 24; j++)
            acc += gm[j] * w1[(size_t)(CDIM + j) * INMLP + n];
        g_bias2[bt * 800 + n] = acc;
    }
}

// ---------------------------------------------------------------------------
// fp16 single-pass GEMM on HMMA; BK=64, 3-stage cp.async pipeline.
// CTA 128x128, 256 threads, 8 warps (2x4), warp tile 64x32.
// EPI: 0 none, 1 +bias[col], 2 +bias2-rowtable+gelu, 3 +residual
// HALFOUT: 1 -> fp16 out, 0 -> fp32 out. PERM: 1 -> GEMM1 A-row permutation
// ---------------------------------------------------------------------------
#define OFF_A 0
#define OFF_B 16384
#define STAGE  32768
#define NSTAGE 3
#define SMEM_SZ (NSTAGE*STAGE)

template<int EPI, int HALFOUT, int PERM>
__global__ void __launch_bounds__(256, 2)
mma_gemm(const __half* __restrict__ A_g,
         const __half* __restrict__ B_g,
         const float* __restrict__ bias,
         const float* __restrict__ res,
         float* __restrict__ C,
         __half* __restrict__ Ch,
         int Nact, int Nstore, int Kpad, int ldC)
{
    extern __shared__ char smem[];
    const uint32_t sb = s2u(smem);
    const int tid = threadIdx.x, wid = tid >> 5, lane = tid & 31;
    const int m0 = blockIdx.y * 128, n0 = blockIdx.x * 128;
    const int wr = wid & 1, wc = wid >> 1;
    const int NCH = Kpad >> 6;

    const int sg0  = tid & 7;
    const int rb   = tid >> 3;
    const uint32_t swz16 = (uint32_t)((sg0 ^ (rb & 7)) << 4);

    const __half* aptr[4];
    const __half* bptr[4];
    #pragma unroll
    for (int i = 0; i < 4; i++) {
        int gr = m0 + i * 32 + rb;
        int ar = gr;
        if (PERM) {
            int b = gr / (S_SP * TT);
            int rem = gr - b * (S_SP * TT);
            int s = rem >> 4, t = rem & 15;
            ar = b * (S_SP * TT) + t * S_SP + s;
        }
        aptr[i] = A_g + (size_t)ar * Kpad + sg0 * 8;
        bptr[i] = B_g + (size_t)(n0 + i * 32 + rb) * Kpad + sg0 * 8;
    }

    auto issue = [&](int c) {
        if (c < NCH) {
            const uint32_t st = sb + (uint32_t)(c % NSTAGE) * STAGE;
            const int k0 = c * 64;
            #pragma unroll
            for (int i = 0; i < 4; i++) {
                uint32_t off = (uint32_t)((i * 32 + rb) * 128) + swz16;
                cp16(st + OFF_A + off, aptr[i] + k0);
                cp16(st + OFF_B + off, bptr[i] + k0);
            }
        }
        asm volatile("cp.async.commit_group;" ::: "memory");
    };

    issue(0); issue(1);

    float acc[4][4][4] = {};

    const int a_r = lane & 15;
    const int a_s = lane >> 4;
    const int b_n = (lane & 7) + ((lane >> 4) << 3);
    const int b_s = (lane >> 3) & 1;

    for (int c = 0; c < NCH; c++) {
        asm volatile("cp.async.wait_group %0;" :: "n"(1) : "memory");
        __syncthreads();
        issue(c + 2);

        const uint32_t st = sb + (uint32_t)(c % NSTAGE) * STAGE;
        #pragma unroll
        for (int step = 0; step < 4; step++) {
            uint32_t Ar[4][4], Br[2][4];
            #pragma unroll
            for (int mi = 0; mi < 4; mi++) {
                int row = wr * 64 + mi * 16 + a_r;
                int ks = step * 2 + a_s;
                uint32_t off = (uint32_t)(row * 128 + ((ks ^ (row & 7)) << 4));
                ldsm4(Ar[mi], st + OFF_A + off);
            }
            #pragma unroll
            for (int np = 0; np < 2; np++) {
                int row = wc * 32 + np * 16 + b_n;
                int ks = step * 2 + b_s;
                uint32_t off = (uint32_t)(row * 128 + ((ks ^ (row & 7)) << 4));
                ldsm4(Br[np], st + OFF_B + off);
            }
            #pragma unroll
            for (int mi = 0; mi < 4; mi++)
                #pragma unroll
                for (int ni = 0; ni < 4; ni++)
                    mma_f16(acc[mi][ni], Ar[mi], &Br[ni >> 1][(ni & 1) * 2]);
        }
        __syncthreads();
    }

    // ---- epilogue ----
    const int gr = lane >> 2, gc = (lane & 3) * 2;
    #pragma unroll
    for (int mi = 0; mi < 4; mi++) {
        #pragma unroll
        for (int h = 0; h < 2; h++) {
            int row = m0 + wr * 64 + mi * 16 + gr + h * 8;
            size_t roff = (size_t)row * ldC;
            const float* brow = bias;
            if (EPI == 2)
                brow = bias + ((size_t)(row / (S_SP * TT)) * 16 + (row & 15)) * 800;
            #pragma unroll
            for (int ni = 0; ni < 4; ni++) {
                int col = n0 + wc * 32 + ni * 8 + gc;
                if (HALFOUT) {
                    if (col >= Nstore) continue;
                } else {
                    if (col >= Nact) continue;
                }
                float v0 = acc[mi][ni][h * 2];
                float v1 = acc[mi][ni][h * 2 + 1];
                if (HALFOUT && col >= Nact) { v0 = 0.f; v1 = 0.f; }
                else {
                    if (EPI == 1) { v0 += bias[col]; v1 += bias[col + 1]; }
                    if (EPI == 2) {
                        v0 = gelu_f(v0 + brow[col]);
                        v1 = gelu_f(v1 + brow[col + 1]);
                    }
                    if (EPI == 3) {
                        v0 += res[roff + col];
                        v1 += res[roff + col + 1];
                    }
                }
                if (HALFOUT) {
                    *reinterpret_cast<uint32_t*>(Ch + roff + col) = pack_f2h(v0, v1);
                } else {
                    *reinterpret_cast<float2*>(C + roff + col) = make_float2(v0, v1);
                }
            }
        }
    }
}

// ---------------------------------------------------------------------------
// Attention via mma.sync: one warp per (bs, head).
// RMSNorm + RoPE in fp32 (shfl), QK^T and P@V on tensor cores.
// ---------------------------------------------------------------------------
__global__ __launch_bounds__(128)
void attn_kernel(const float* __restrict__ q_gamma,
                 const float* __restrict__ k_gamma)
{
    __shared__ __half qs[4][TT][40];
    __shared__ __half ks[4][TT][40];
    __shared__ __half vst[4][HDIM][18];

    int warp = threadIdx.x >> 5;
    int lane = threadIdx.x & 31;
    int gw = blockIdx.x * 4 + warp;
    int head = gw % HEADS;
    int bs   = gw / HEADS;
    int b_idx = bs / S_SP;
    int s     = bs % S_SP;

    float q[TT], k[TT], v[TT];
    #pragma unroll
    for (int t = 0; t < TT; t++) {
        size_t base = ((size_t)(bs * TT + t)) * (3 * CDIM) + head * HDIM + lane;
        q[t] = __half2float(g_qkv[base]);
        k[t] = __half2float(g_qkv[base + CDIM]);
        v[t] = __half2float(g_qkv[base + 2 * CDIM]);
    }

    float qg = q_gamma[lane], kg = k_gamma[lane];
    float freq = 0.0f;
    if (lane < 24) {
        int p = lane >> 1;
        freq = exp2f(-8.0f * (float)(2 * p) / 24.0f);
    }
    const float scale = 0.17677669529663687f;   // folded into q

    #pragma unroll
    for (int t = 0; t < TT; t++) {
        float sq = q[t] * q[t];
        float sk = k[t] * k[t];
        #pragma unroll
        for (int o = 16; o > 0; o >>= 1) {
            sq += __shfl_xor_sync(0xffffffffu, sq, o);
            sk += __shfl_xor_sync(0xffffffffu, sk, o);
        }
        float qn = q[t] * rsqrtf(sq * (1.0f / 32.0f) + 1e-6f) * qg;
        float kn = k[t] * rsqrtf(sk * (1.0f / 32.0f) + 1e-6f) * kg;

        float c = 1.0f, sn = 0.0f;
        if (lane < 24) {
            float ang = freq * (float)t;
            c = cosf(ang);
            sn = sinf(ang);
        }
        float qr = __shfl_xor_sync(0xffffffffu, qn, 1);
        float kr = __shfl_xor_sync(0xffffffffu, kn, 1);
        qr = (lane & 1) ? qr : -qr;
        kr = (lane & 1) ? kr : -kr;

        qs[warp][t][lane] = __float2half((qn * c + qr * sn) * scale);
        ks[warp][t][lane] = __float2half(kn * c + kr * sn);
        vst[warp][lane][t] = __float2half(v[t]);
    }
    __syncwarp();

    const int r = lane >> 2, q4 = lane & 3;

    // ---- scores: S(16x16) = Q(16x32) @ K^T, 2 k-chunks x 2 n-tiles ----
    float sc[2][4] = {};
    #pragma unroll
    for (int c = 0; c < 2; c++) {
        uint32_t a[4];
        a[0] = *reinterpret_cast<const uint32_t*>(&qs[warp][r    ][c*16 + 2*q4]);
        a[1] = *reinterpret_cast<const uint32_t*>(&qs[warp][r + 8][c*16 + 2*q4]);
        a[2] = *reinterpret_cast<const uint32_t*>(&qs[warp][r    ][c*16 + 2*q4 + 8]);
        a[3] = *reinterpret_cast<const uint32_t*>(&qs[warp][r + 8][c*16 + 2*q4 + 8]);
        #pragma unroll
        for (int nt = 0; nt < 2; nt++) {
            uint32_t b[2];
            b[0] = *reinterpret_cast<const uint32_t*>(&ks[warp][nt*8 + r][c*16 + 2*q4]);
            b[1] = *reinterpret_cast<const uint32_t*>(&ks[warp][nt*8 + r][c*16 + 2*q4 + 8]);
            mma_f16(sc[nt], a, b);
        }
    }

    // ---- softmax over 16 cols; row r: sc[*][0..1], row r+8: sc[*][2..3] ----
    float m0 = fmaxf(fmaxf(sc[0][0], sc[0][1]), fmaxf(sc[1][0], sc[1][1]));
    float m1 = fmaxf(fmaxf(sc[0][2], sc[0][3]), fmaxf(sc[1][2], sc[1][3]));
    m0 = fmaxf(m0, __shfl_xor_sync(0xffffffffu, m0, 1));
    m0 = fmaxf(m0, __shfl_xor_sync(0xffffffffu, m0, 2));
    m1 = fmaxf(m1, __shfl_xor_sync(0xffffffffu, m1, 1));
    m1 = fmaxf(m1, __shfl_xor_sync(0xffffffffu, m1, 2));
    #pragma unroll
    for (int nt = 0; nt < 2; nt++) {
        sc[nt][0] = __expf(sc[nt][0] - m0);
        sc[nt][1] = __expf(sc[nt][1] - m0);
        sc[nt][2] = __expf(sc[nt][2] - m1);
        sc[nt][3] = __expf(sc[nt][3] - m1);
    }
    float s0 = sc[0][0] + sc[0][1] + sc[1][0] + sc[1][1];
    float s1 = sc[0][2] + sc[0][3] + sc[1][2] + sc[1][3];
    s0 += __shfl_xor_sync(0xffffffffu, s0, 1);
    s0 += __shfl_xor_sync(0xffffffffu, s0, 2);
    s1 += __shfl_xor_sync(0xffffffffu, s1, 1);
    s1 += __shfl_xor_sync(0xffffffffu, s1, 2);
    float i0 = 1.0f / s0, i1 = 1.0f / s1;

    // ---- P fragment (A-layout, direct repack of C regs) ----
    uint32_t pa[4];
    pa[0] = pack_f2h(sc[0][0] * i0, sc[0][1] * i0);
    pa[1] = pack_f2h(sc[0][2] * i1, sc[0][3] * i1);
    pa[2] = pack_f2h(sc[1][0] * i0, sc[1][1] * i0);
    pa[3] = pack_f2h(sc[1][2] * i1, sc[1][3] * i1);

    // ---- out(16x32) = P @ V; 4 d-tiles of n8 ----
    size_t row0 = ((size_t)b_idx * (TT * S_SP) + (size_t)r * S_SP + s) * CDIM
                  + head * HDIM;
    size_t row1 = row0 + (size_t)8 * S_SP * CDIM;
    #pragma unroll
    for (int dt = 0; dt < 4; dt++) {
        float o[4] = {0.f, 0.f, 0.f, 0.f};
        uint32_t b[2];
        b[0] = *reinterpret_cast<const uint32_t*>(&vst[warp][dt*8 + r][2*q4]);
        b[1] = *reinterpret_cast<const uint32_t*>(&vst[warp][dt*8 + r][2*q4 + 8]);
        mma_f16(o, pa, b);
        *reinterpret_cast<uint32_t*>(g_at + row0 + dt*8 + 2*q4) = pack_f2h(o[0], o[1]);
        *reinterpret_cast<uint32_t*>(g_at + row1 + dt*8 + 2*q4) = pack_f2h(o[2], o[3]);
    }
}

// ---------------------------------------------------------------------------
extern "C" void kernel_launch(void* const* d_in, const int* in_sizes, int n_in,
                              void* d_out, int out_size)
{
    const float* mouse = (const float*)d_in[0];
    const float* x     = (const float*)d_in[2];
    const float* w1    = (const float*)d_in[3];
    const float* b1    = (const float*)d_in[4];
    const float* w2    = (const float*)d_in[5];
    const float* b2    = (const float*)d_in[6];
    const float* qkvw  = (const float*)d_in[7];
    const float* qg    = (const float*)d_in[8];
    const float* kg    = (const float*)d_in[9];
    const float* pw    = (const float*)d_in[10];
    float* out = (float*)d_out;

    cudaFuncSetAttribute(mma_gemm<2,1,1>, cudaFuncAttributeMaxDynamicSharedMemorySize, SMEM_SZ);
    cudaFuncSetAttribute(mma_gemm<1,1,0>, cudaFuncAttributeMaxDynamicSharedMemorySize, SMEM_SZ);
    cudaFuncSetAttribute(mma_gemm<0,1,0>, cudaFuncAttributeMaxDynamicSharedMemorySize, SMEM_SZ);
    cudaFuncSetAttribute(mma_gemm<3,0,0>, cudaFuncAttributeMaxDynamicSharedMemorySize, SMEM_SZ);

    __half *w1p, *w2p, *w3p, *w4p;
    cudaGetSymbolAddress((void**)&w1p, g_w1);
    cudaGetSymbolAddress((void**)&w2p, g_w2);
    cudaGetSymbolAddress((void**)&w3p, g_w3);
    cudaGetSymbolAddress((void**)&w4p, g_w4);

    __half *x16p, *hp, *fp, *atp, *qkvP;
    cudaGetSymbolAddress((void**)&x16p, g_x16);
    cudaGetSymbolAddress((void**)&hp, g_h);
    cudaGetSymbolAddress((void**)&fp, g_f);
    cudaGetSymbolAddress((void**)&atp, g_at);
    cudaGetSymbolAddress((void**)&qkvP, g_qkv);
    float* bias2p;
    cudaGetSymbolAddress((void**)&bias2p, g_bias2);

    dim3 cb(32, 8);
    conv_weight<<<dim3(25, 24), cb>>>(w1,   w1p, 768, 792,  768);   // first 768 k-rows
    conv_weight<<<dim3(24, 26), cb>>>(w2,   w2p, 792, 768,  KP1);
    conv_weight<<<dim3(72, 24), cb>>>(qkvw, w3p, 768, 2304, 768);
    conv_weight<<<dim3(24, 24), cb>>>(pw,   w4p, 768, 768,  768);

    convert_x<<<2048, 256>>>(x);
    build_bias2<<<32, 256>>>(mouse, w1, b1);

    // h = gelu(x16 @ w1[:768] + bias2) -> fp16  N=792 (7 tiles), K=768, PERM
    mma_gemm<2,1,1><<<dim3(7, NROWS/128), 256, SMEM_SZ>>>(
        x16p, w1p, bias2p, nullptr, nullptr, hp, 792, KP1, CDIM, KP1);
    // feat = h @ w2 + b2 -> fp16                N=768, K=832
    mma_gemm<1,1,0><<<dim3(6, NROWS/128), 256, SMEM_SZ>>>(
        hp, w2p, b2, nullptr, nullptr, fp, 768, 768, KP1, CDIM);
    // qkv = feat @ qkv_w -> fp16                N=2304, K=768
    mma_gemm<0,1,0><<<dim3(18, NROWS/128), 256, SMEM_SZ>>>(
        fp, w3p, nullptr, nullptr, nullptr, qkvP, 2304, 2304, 768, 3*CDIM);

    attn_kernel<<<(BATCH * S_SP * HEADS) / 4, 128>>>(qg, kg);

    // out = x + attn @ proj_w -> fp32           N=768, K=768
    mma_gemm<3,0,0><<<dim3(6, NROWS/128), 256, SMEM_SZ>>>(
        atp, w4p, nullptr, x, out, nullptr, 768, 768, 768, CDIM);

    (void)in_sizes; (void)n_in; (void)out_size;
}